// round 14
// baseline (speedup 1.0000x reference)
#include <cuda_runtime.h>
#include <cuda_fp16.h>
#include <cstdint>

// Problem dims
#define BATCH 4
#define SEQ   2048
#define EMBED 1024
#define HID   4096
#define VOCAB 32000

// ---------------------------------------------------------------------------
// PTX helpers (plain sm_103-legal: cp.async / ldmatrix / mma.sync only)
// ---------------------------------------------------------------------------
__device__ __forceinline__ uint32_t smem_u32(const void* p) {
    uint32_t a;
    asm("{ .reg .u64 t; cvta.to.shared.u64 t, %1; cvt.u32.u64 %0, t; }" : "=r"(a) : "l"(p));
    return a;
}
#define CP_ASYNC16(s, g) \
    asm volatile("cp.async.cg.shared.global [%0], [%1], 16;\n" :: "r"(s), "l"(g))
#define CP_COMMIT() asm volatile("cp.async.commit_group;\n" ::: "memory")
#define CP_WAIT1()  asm volatile("cp.async.wait_group 1;\n" ::: "memory")

__device__ __forceinline__ void ldsm4(uint32_t* r, uint32_t a) {
    asm volatile("ldmatrix.sync.aligned.m8n8.x4.shared.b16 {%0,%1,%2,%3}, [%4];"
        : "=r"(r[0]), "=r"(r[1]), "=r"(r[2]), "=r"(r[3]) : "r"(a));
}
__device__ __forceinline__ void mma16816(float* c, const uint32_t* a, const uint32_t* b) {
    asm volatile(
        "mma.sync.aligned.m16n8k16.row.col.f32.f16.f16.f32 "
        "{%0,%1,%2,%3}, {%4,%5,%6,%7}, {%8,%9}, {%0,%1,%2,%3};"
        : "+f"(c[0]), "+f"(c[1]), "+f"(c[2]), "+f"(c[3])
        : "r"(a[0]), "r"(a[1]), "r"(a[2]), "r"(a[3]), "r"(b[0]), "r"(b[1]));
}

// 128B-row SW128 swizzle: row r, 16B-chunk q (0..7) -> byte offset in tile
#define SWZ(r, q) ((uint32_t)((r) * 128 + ((((q) ^ ((r) & 7))) << 4)))

// fp16 hi/lo split (hi+lo covers ~22 mantissa bits of the fp32 value)
__device__ __forceinline__ void hsplit(float v, __half& h, __half& l) {
    h = __float2half_rn(v);
    l = __float2half_rn(v - __half2float(h));
}

// ---------------------------------------------------------------------------
// Scratch (device globals)
// ---------------------------------------------------------------------------
__device__ __half g_xhi   [BATCH * SEQ * EMBED];
__device__ __half g_xlo   [BATCH * SEQ * EMBED];
__device__ __half g_xThi  [BATCH * EMBED * SEQ];
__device__ float  g_scores[BATCH * SEQ * SEQ];
__device__ __half g_whi   [BATCH * SEQ * SEQ];
__device__ __half g_atthi [BATCH * SEQ * EMBED];
__device__ __half g_hidhi [BATCH * SEQ * HID];
__device__ __half g_W1t   [HID * EMBED];
__device__ __half g_W2t   [(size_t)VOCAB * HID];

// ---------------------------------------------------------------------------
// Embedding gather: fp16 hi/lo only
// ---------------------------------------------------------------------------
__global__ void embed_kernel(const int* __restrict__ ids, const float* __restrict__ emb,
                             __half* __restrict__ xhi, __half* __restrict__ xlo) {
    int row = blockIdx.x;
    int id  = ids[row];
    int t = threadIdx.x;
    float4 v = reinterpret_cast<const float4*>(emb + (long)id * EMBED)[t];
    __half h0, l0, h1, l1, h2, l2, h3, l3;
    hsplit(v.x, h0, l0); hsplit(v.y, h1, l1); hsplit(v.z, h2, l2); hsplit(v.w, h3, l3);
    __half2* dh = reinterpret_cast<__half2*>(xhi + (long)row * EMBED) + t * 2;
    __half2* dl = reinterpret_cast<__half2*>(xlo + (long)row * EMBED) + t * 2;
    dh[0] = __halves2half2(h0, h1); dh[1] = __halves2half2(h2, h3);
    dl[0] = __halves2half2(l0, l1); dl[1] = __halves2half2(l2, l3);
}

// ---------------------------------------------------------------------------
// xT gather-transpose: xThi[b][e][s] = fp16(emb[ids[b][s]][e])
// 32x32 tiles, float2 loads, __half2 stores. Block (16,16).
// ---------------------------------------------------------------------------
__global__ void xt_gather_kernel(const int* __restrict__ ids, const float* __restrict__ emb,
                                 __half* __restrict__ o) {
    __shared__ float t[32][33];
    long z = blockIdx.z;
    const int* idz = ids + z * SEQ;
    o += z * (long)EMBED * SEQ;
    int c0 = blockIdx.x * 32;   // embed dims
    int r0 = blockIdx.y * 32;   // tokens
    int tx = threadIdx.x, ty = threadIdx.y;
    #pragma unroll
    for (int i = 0; i < 32; i += 16) {
        int id = idz[r0 + ty + i];
        float2 v = *reinterpret_cast<const float2*>(emb + (long)id * EMBED + c0 + 2 * tx);
        t[ty + i][2 * tx]     = v.x;
        t[ty + i][2 * tx + 1] = v.y;
    }
    __syncthreads();
    #pragma unroll
    for (int i = 0; i < 32; i += 16) {
        int cc = ty + i;
        __half2 h = __halves2half2(__float2half_rn(t[2 * tx][cc]),
                                   __float2half_rn(t[2 * tx + 1][cc]));
        *reinterpret_cast<__half2*>(o + (long)(c0 + cc) * SEQ + r0 + 2 * tx) = h;
    }
}

// ---------------------------------------------------------------------------
// Softmax rows (fp32 in) -> fp16 hi weights only
// ---------------------------------------------------------------------------
__global__ __launch_bounds__(256)
void softmax_kernel(const float* __restrict__ scores, __half* __restrict__ whi) {
    __shared__ float red[256];
    const float* row = scores + (long)blockIdx.x * SEQ;
    __half* oh = whi + (long)blockIdx.x * SEQ;
    const int tid = threadIdx.x;

    float v[8];
    float lmax = -3.402823466e+38f;
    #pragma unroll
    for (int i = 0; i < 8; i++) { v[i] = row[tid + i * 256]; lmax = fmaxf(lmax, v[i]); }
    red[tid] = lmax; __syncthreads();
    #pragma unroll
    for (int s = 128; s > 0; s >>= 1) { if (tid < s) red[tid] = fmaxf(red[tid], red[tid + s]); __syncthreads(); }
    float m = red[0]; __syncthreads();

    float lsum = 0.f;
    #pragma unroll
    for (int i = 0; i < 8; i++) { v[i] = __expf(v[i] - m); lsum += v[i]; }
    red[tid] = lsum; __syncthreads();
    #pragma unroll
    for (int s = 128; s > 0; s >>= 1) { if (tid < s) red[tid] += red[tid + s]; __syncthreads(); }
    float inv = 1.f / red[0];
    #pragma unroll
    for (int i = 0; i < 8; i++)
        oh[tid + i * 256] = __float2half_rn(v[i] * inv);
}

// ---------------------------------------------------------------------------
// 3-term split-fp16 symmetric GEMM (scores):  C = A*A^T, upper-tri + mirror.
// CTA 128x128, BK=64, 8 warps, 3 stages.
// Tail: fused W1/W2 transpose-convert (fp32 [R,C] -> fp16 [C,R]) — each CTA
// handles a slice of the 32x32 tiles, overlapped across scores waves.
// ---------------------------------------------------------------------------
#define BMT 128
#define BKT 64
#define TILE_BYTES 16384    // 128 rows x 128 B

__device__ __forceinline__ void load_chunk_sym(uint32_t sbase, int st,
    const __half* __restrict__ gA0, const __half* __restrict__ gA1,
    const __half* __restrict__ gB0, const __half* __restrict__ gB1,
    int K, int k0, int tid)
{
    uint32_t s0 = sbase + (uint32_t)(st * 4 * TILE_BYTES);
    #pragma unroll
    for (int it = 0; it < 4; it++) {
        int idx = tid + it * 256;
        int r = idx >> 3, c = idx & 7;
        uint32_t so = SWZ(r, c);
        long go = (long)r * K + k0 + c * 8;
        CP_ASYNC16(s0 + 0 * TILE_BYTES + so, gA0 + go);
        CP_ASYNC16(s0 + 1 * TILE_BYTES + so, gA1 + go);
        CP_ASYNC16(s0 + 2 * TILE_BYTES + so, gB0 + go);
        CP_ASYNC16(s0 + 3 * TILE_BYTES + so, gB1 + go);
    }
}

__global__ __launch_bounds__(256, 1)
void hgemm_sym(const __half* __restrict__ A0, const __half* __restrict__ A1,
               float* __restrict__ Cf, int N, int K, long sA, long sC, int ntm,
               const float* __restrict__ W1, const float* __restrict__ W2,
               __half* __restrict__ w1t, __half* __restrict__ w2t)
{
    extern __shared__ char smem[];
    const uint32_t sbase = smem_u32(smem);
    const int tid  = threadIdx.x;
    const int wid  = tid >> 5, lane = tid & 31;
    const int wm   = wid & 1,  wn   = wid >> 1;

    int t0 = blockIdx.x, i0 = 0;
    while (t0 >= ntm - i0) { t0 -= ntm - i0; i0++; }
    int pm = i0, pn = i0 + t0;
    long m0 = (long)pm * BMT, n0 = (long)pn * BMT;
    long zb = blockIdx.z;
    const __half* gA0 = A0 + zb * sA + m0 * K;
    const __half* gA1 = A1 + zb * sA + m0 * K;
    const __half* gB0 = A0 + zb * sA + n0 * K;
    const __half* gB1 = A1 + zb * sA + n0 * K;

    float acc[4][4][4];
    #pragma unroll
    for (int i = 0; i < 4; i++)
        #pragma unroll
        for (int j = 0; j < 4; j++)
            #pragma unroll
            for (int k = 0; k < 4; k++) acc[i][j][k] = 0.f;

    const int ar = lane & 15;
    const int ak = (lane >> 4) << 3;
    const int br = ((lane >> 4) << 3) + (lane & 7);
    const int bk = ((lane >> 3) & 1) << 3;

    load_chunk_sym(sbase, 0, gA0, gA1, gB0, gB1, K, 0, tid);   CP_COMMIT();
    load_chunk_sym(sbase, 1, gA0, gA1, gB0, gB1, K, BKT, tid); CP_COMMIT();

    const int nc = K / BKT;
    for (int c = 0; c < nc; c++) {
        CP_WAIT1();
        __syncthreads();
        if (c + 2 < nc)
            load_chunk_sym(sbase, (c + 2) % 3, gA0, gA1, gB0, gB1, K, (c + 2) * BKT, tid);
        CP_COMMIT();

        uint32_t s0 = sbase + (uint32_t)((c % 3) * 4 * TILE_BYTES);
        #pragma unroll
        for (int kb = 0; kb < BKT; kb += 16) {
            uint32_t a0f[4][4], a1f[4][4], b0f[2][4], b1f[2][4];
            int aq = (kb + ak) >> 3;
            int bq = (kb + bk) >> 3;
            #pragma unroll
            for (int mt = 0; mt < 4; mt++) {
                int r = wm * 64 + mt * 16 + ar;
                uint32_t ad = s0 + SWZ(r, aq);
                ldsm4(a0f[mt], ad);
                ldsm4(a1f[mt], ad + TILE_BYTES);
            }
            #pragma unroll
            for (int nt = 0; nt < 2; nt++) {
                int r = wn * 32 + nt * 16 + br;
                uint32_t bd = s0 + 2 * TILE_BYTES + SWZ(r, bq);
                ldsm4(b0f[nt], bd);
                ldsm4(b1f[nt], bd + TILE_BYTES);
            }
            #pragma unroll
            for (int mt = 0; mt < 4; mt++)
                #pragma unroll
                for (int n8 = 0; n8 < 4; n8++) {
                    const uint32_t* b = &b0f[n8 >> 1][(n8 & 1) * 2];
                    mma16816(acc[mt][n8], a0f[mt], b);
                    mma16816(acc[mt][n8], a1f[mt], b);
                    mma16816(acc[mt][n8], a0f[mt], &b1f[n8 >> 1][(n8 & 1) * 2]);
                }
        }
    }

    // ---- epilogue (direct tile) ----
    long zC = zb * sC;
    int rb = lane >> 2;
    int cb = (lane & 3) * 2;
    #pragma unroll
    for (int mt = 0; mt < 4; mt++) {
        #pragma unroll
        for (int n8 = 0; n8 < 4; n8++) {
            long col = n0 + wn * 32 + n8 * 8 + cb;
            #pragma unroll
            for (int h = 0; h < 2; h++) {
                long row = m0 + wm * 64 + mt * 16 + rb + h * 8;
                *reinterpret_cast<float2*>(Cf + zC + row * (long)N + col) =
                    make_float2(acc[mt][n8][h * 2 + 0], acc[mt][n8][h * 2 + 1]);
            }
        }
    }

    // ---- mirror transposed tile at (pn, pm) ----
    if (pm != pn) {
        __syncthreads();
        float* stg = reinterpret_cast<float*>(smem);   // 128 x 129 floats
        #pragma unroll
        for (int mt = 0; mt < 4; mt++)
            #pragma unroll
            for (int n8 = 0; n8 < 4; n8++) {
                int colb = wn * 32 + n8 * 8 + cb;
                #pragma unroll
                for (int h = 0; h < 2; h++) {
                    int rowb = wm * 64 + mt * 16 + rb + h * 8;
                    stg[rowb * 129 + colb]     = acc[mt][n8][h * 2 + 0];
                    stg[rowb * 129 + colb + 1] = acc[mt][n8][h * 2 + 1];
                }
            }
        __syncthreads();
        #pragma unroll
        for (int it = 0; it < 64; it++) {
            int idx = tid + it * 256;
            int rr = idx >> 7, cc = idx & 127;
            Cf[zC + (n0 + rr) * (long)N + m0 + cc] = stg[cc * 129 + rr];
        }
    }

    // ---- fused weight transpose-convert tail ----
    // W1 [E,H] -> w1t [H,E]; W2 [H,V] -> w2t [V,H]; 32x32 fp32 tiles via smem.
    {
        const int NT1 = (HID / 32) * (EMBED / 32);        // 4096
        const int NT2 = (VOCAB / 32) * (HID / 32);        // 128000
        const int TOT = NT1 + NT2;                        // 132096
        int nCta = gridDim.x * gridDim.z;                 // 544
        int cid  = (int)zb * gridDim.x + blockIdx.x;
        int per  = (TOT + nCta - 1) / nCta;
        int lo = cid * per;
        int hi = lo + per; if (hi > TOT) hi = TOT;

        float* ts = reinterpret_cast<float*>(smem);       // 32 x 33 floats
        const int lr  = tid >> 3;          // load row 0..31
        const int lc4 = (tid & 7) * 4;     // load col group
        const int sc  = tid >> 3;          // store col (of transposed) 0..31
        const int sr4 = (tid & 7) * 4;     // store row group

        for (int T = lo; T < hi; T++) {
            const float* in; __half* outp; int R, C, tr, tc;
            if (T < NT1) {
                in = W1; outp = w1t; R = EMBED; C = HID;
                tc = T & (HID / 32 - 1); tr = T >> 7;              // HID/32=128
            } else {
                int T2 = T - NT1;
                in = W2; outp = w2t; R = HID; C = VOCAB;
                tc = T2 % (VOCAB / 32); tr = T2 / (VOCAB / 32);
            }
            int c0 = tc * 32, r0 = tr * 32;
            __syncthreads();
            float4 v = *reinterpret_cast<const float4*>(in + (long)(r0 + lr) * C + c0 + lc4);
            ts[lr * 33 + lc4 + 0] = v.x;
            ts[lr * 33 + lc4 + 1] = v.y;
            ts[lr * 33 + lc4 + 2] = v.z;
            ts[lr * 33 + lc4 + 3] = v.w;
            __syncthreads();
            __half2 p0 = __halves2half2(__float2half_rn(ts[(sr4 + 0) * 33 + sc]),
                                        __float2half_rn(ts[(sr4 + 1) * 33 + sc]));
            __half2 p1 = __halves2half2(__float2half_rn(ts[(sr4 + 2) * 33 + sc]),
                                        __float2half_rn(ts[(sr4 + 3) * 33 + sc]));
            __half2* dst = reinterpret_cast<__half2*>(outp + (long)(c0 + sc) * R + r0 + sr4);
            dst[0] = p0;
            dst[1] = p1;
        }
    }
}

// ---------------------------------------------------------------------------
// 1-term HMMA GEMM (attended, FFN1, FFN2): 2 CTAs/SM, CTA 128x128, BK=64,
// 8 warps, 3 stages (96 KB/CTA).  OUT=0: fp32.  OUT=1: fp16 hi.  Batched via z.
// ---------------------------------------------------------------------------
#define F2_STAGE (2 * TILE_BYTES)      // A tile + B tile = 32 KB
#define F2_SMEM  (3 * F2_STAGE)        // 98304

__device__ __forceinline__ void load_chunk_1t(uint32_t sbase, int st,
    const __half* __restrict__ gA, const __half* __restrict__ gB,
    int K, int k0, int tid)
{
    uint32_t s0 = sbase + (uint32_t)(st * F2_STAGE);
    #pragma unroll
    for (int it = 0; it < 4; it++) {
        int idx = tid + it * 256;
        int r = idx >> 3, c = idx & 7;
        uint32_t so = SWZ(r, c);
        long go = (long)r * K + k0 + c * 8;
        CP_ASYNC16(s0 + so, gA + go);
        CP_ASYNC16(s0 + TILE_BYTES + so, gB + go);
    }
}

template<int OUT, bool BIAS, bool RELU>
__global__ __launch_bounds__(256, 2)
void hgemm_1t(const __half* __restrict__ A0, const __half* __restrict__ B0,
              const float* __restrict__ bias,
              float* __restrict__ Cf, __half* __restrict__ Chi,
              int M, int N, int K, long sA, long sB, long sC, int ntm)
{
    extern __shared__ char smem[];
    const uint32_t sbase = smem_u32(smem);
    const int tid  = threadIdx.x;
    const int wid  = tid >> 5, lane = tid & 31;
    const int wm   = wid & 1,  wn   = wid >> 1;

    int pm = blockIdx.x % ntm, pn = blockIdx.x / ntm;
    long m0 = (long)pm * 128, n0 = (long)pn * 128;
    long zb = blockIdx.z;
    const __half* gA = A0 + zb * sA + m0 * K;
    const __half* gB = B0 + zb * sB + n0 * K;

    float acc[4][4][4];
    #pragma unroll
    for (int i = 0; i < 4; i++)
        #pragma unroll
        for (int j = 0; j < 4; j++)
            #pragma unroll
            for (int k = 0; k < 4; k++) acc[i][j][k] = 0.f;

    const int ar = lane & 15;
    const int ak = (lane >> 4) << 3;
    const int br = ((lane >> 4) << 3) + (lane & 7);
    const int bk = ((lane >> 3) & 1) << 3;

    load_chunk_1t(sbase, 0, gA, gB, K, 0, tid);    CP_COMMIT();
    load_chunk_1t(sbase, 1, gA, gB, K, BKT, tid);  CP_COMMIT();

    const int nc = K / BKT;
    for (int c = 0; c < nc; c++) {
        CP_WAIT1();
        __syncthreads();
        if (c + 2 < nc)
            load_chunk_1t(sbase, (c + 2) % 3, gA, gB, K, (c + 2) * BKT, tid);
        CP_COMMIT();

        uint32_t s0 = sbase + (uint32_t)((c % 3) * F2_STAGE);
        #pragma unroll
        for (int kb = 0; kb < BKT; kb += 16) {
            uint32_t af[4][4], bf[2][4];
            int aq = (kb + ak) >> 3;
            int bq = (kb + bk) >> 3;
            #pragma unroll
            for (int mt = 0; mt < 4; mt++) {
                int r = wm * 64 + mt * 16 + ar;
                ldsm4(af[mt], s0 + SWZ(r, aq));
            }
            #pragma unroll
            for (int nt = 0; nt < 2; nt++) {
                int r = wn * 32 + nt * 16 + br;
                ldsm4(bf[nt], s0 + TILE_BYTES + SWZ(r, bq));
            }
            #pragma unroll
            for (int mt = 0; mt < 4; mt++)
                #pragma unroll
                for (int n8 = 0; n8 < 4; n8++)
                    mma16816(acc[mt][n8], af[mt], &bf[n8 >> 1][(n8 & 1) * 2]);
        }
    }

    // ---- epilogue ----
    long zC = zb * sC;
    int rb = lane >> 2;
    int cb = (lane & 3) * 2;
    #pragma unroll
    for (int mt = 0; mt < 4; mt++) {
        #pragma unroll
        for (int n8 = 0; n8 < 4; n8++) {
            long col = n0 + wn * 32 + n8 * 8 + cb;
            float bv0 = 0.f, bv1 = 0.f;
            if (BIAS) { bv0 = bias[col]; bv1 = bias[col + 1]; }
            #pragma unroll
            for (int h = 0; h < 2; h++) {
                long row = m0 + wm * 64 + mt * 16 + rb + h * 8;
                float v0 = acc[mt][n8][h * 2 + 0] + bv0;
                float v1 = acc[mt][n8][h * 2 + 1] + bv1;
                if (RELU) { v0 = fmaxf(v0, 0.f); v1 = fmaxf(v1, 0.f); }
                long o = row * (long)N + col;
                if (OUT == 0) {
                    *reinterpret_cast<float2*>(Cf + zC + o) = make_float2(v0, v1);
                } else {
                    *reinterpret_cast<__half2*>(Chi + zC + o) =
                        __halves2half2(__float2half_rn(v0), __float2half_rn(v1));
                }
            }
        }
    }
}

// ---------------------------------------------------------------------------
// Launch
// ---------------------------------------------------------------------------
extern "C" void kernel_launch(void* const* d_in, const int* in_sizes, int n_in,
                              void* d_out, int out_size) {
    const int*   ids = (const int*)  d_in[0];
    const float* emb = (const float*)d_in[1];
    const float* W1  = (const float*)d_in[2];
    const float* b1  = (const float*)d_in[3];
    const float* W2  = (const float*)d_in[4];
    const float* b2  = (const float*)d_in[5];
    float* out = (float*)d_out;

    float* scores;
    __half *xhi, *xlo, *xThi, *whi, *athi, *hdhi, *w1t, *w2t;
    cudaGetSymbolAddress((void**)&scores, g_scores);
    cudaGetSymbolAddress((void**)&xhi,    g_xhi);
    cudaGetSymbolAddress((void**)&xlo,    g_xlo);
    cudaGetSymbolAddress((void**)&xThi,   g_xThi);
    cudaGetSymbolAddress((void**)&whi,    g_whi);
    cudaGetSymbolAddress((void**)&athi,   g_atthi);
    cudaGetSymbolAddress((void**)&hdhi,   g_hidhi);
    cudaGetSymbolAddress((void**)&w1t,    g_W1t);
    cudaGetSymbolAddress((void**)&w2t,    g_W2t);

    const int SM3 = 4 * 3 * TILE_BYTES;   // scores: 196608
    cudaFuncSetAttribute(hgemm_sym, cudaFuncAttributeMaxDynamicSharedMemorySize, SM3);
    cudaFuncSetAttribute(hgemm_1t<1, false, false>, cudaFuncAttributeMaxDynamicSharedMemorySize, F2_SMEM);
    cudaFuncSetAttribute(hgemm_1t<1, true,  true >, cudaFuncAttributeMaxDynamicSharedMemorySize, F2_SMEM);
    cudaFuncSetAttribute(hgemm_1t<0, true,  false>, cudaFuncAttributeMaxDynamicSharedMemorySize, F2_SMEM);

    // 0) embedding -> x hi/lo fp16
    embed_kernel<<<BATCH * SEQ, 256>>>(ids, emb, xhi, xlo);

    // 1) xT single fp16 via gather-transpose from emb
    {
        dim3 grid(EMBED / 32, SEQ / 32, BATCH);
        xt_gather_kernel<<<grid, dim3(16, 16)>>>(ids, emb, xThi);
    }

    // 2) scores = x @ x^T (3-term symmetric, upper-tri + mirror)
    //    + fused W1t/W2t transpose-convert in CTA tails
    {
        const int ntm = SEQ / BMT;                 // 16
        dim3 grid(ntm * (ntm + 1) / 2, 1, BATCH);  // 136 x 4
        hgemm_sym<<<grid, 256, SM3>>>(
            xhi, xlo, scores, SEQ, EMBED, (long)SEQ * EMBED, (long)SEQ * SEQ, ntm,
            W1, W2, w1t, w2t);
    }

    // 3) softmax -> w hi
    softmax_kernel<<<BATCH * SEQ, 256>>>(scores, whi);

    // 4) attended = w @ x  (1-term NT, 2CTA/SM, fp16 hi out)  M=2048 N=1024 K=2048
    {
        dim3 grid((SEQ / 128) * (EMBED / 128), 1, BATCH);
        hgemm_1t<1, false, false><<<grid, 256, F2_SMEM>>>(
            whi, xThi, nullptr, nullptr, athi,
            SEQ, EMBED, SEQ,
            (long)SEQ * SEQ, (long)EMBED * SEQ, (long)SEQ * EMBED,
            SEQ / 128);
    }

    // 5) hidden = relu(att @ W1 + b1)  (1-term NT, 2CTA/SM, fp16 hi out)  M=8192 N=4096 K=1024
    {
        dim3 grid(((BATCH * SEQ) / 128) * (HID / 128), 1, 1);
        hgemm_1t<1, true, true><<<grid, 256, F2_SMEM>>>(
            athi, w1t, b1, nullptr, hdhi,
            BATCH * SEQ, HID, EMBED, 0, 0, 0,
            (BATCH * SEQ) / 128);
    }

    // 6) logits = hidden @ W2 + b2  (1-term NT, 2CTA/SM, fp32 out)  M=8192 N=32000 K=4096
    {
        dim3 grid(((BATCH * SEQ) / 128) * (VOCAB / 128), 1, 1);
        hgemm_1t<0, true, false><<<grid, 256, F2_SMEM>>>(
            hdhi, w2t, b2, out, nullptr,
            BATCH * SEQ, VOCAB, HID, 0, 0, 0,
            (BATCH * SEQ) / 128);
    }
}

// round 15
// speedup vs baseline: 1.1073x; 1.1073x over previous
#include <cuda_runtime.h>
#include <cuda_fp16.h>
#include <cstdint>

// Problem dims
#define BATCH 4
#define SEQ   2048
#define EMBED 1024
#define HID   4096
#define VOCAB 32000

// ---------------------------------------------------------------------------
// PTX helpers (plain sm_103-legal: cp.async / ldmatrix / mma.sync only)
// ---------------------------------------------------------------------------
__device__ __forceinline__ uint32_t smem_u32(const void* p) {
    uint32_t a;
    asm("{ .reg .u64 t; cvta.to.shared.u64 t, %1; cvt.u32.u64 %0, t; }" : "=r"(a) : "l"(p));
    return a;
}
#define CP_ASYNC16(s, g) \
    asm volatile("cp.async.cg.shared.global [%0], [%1], 16;\n" :: "r"(s), "l"(g))
#define CP_COMMIT() asm volatile("cp.async.commit_group;\n" ::: "memory")
#define CP_WAIT1()  asm volatile("cp.async.wait_group 1;\n" ::: "memory")

__device__ __forceinline__ void ldsm4(uint32_t* r, uint32_t a) {
    asm volatile("ldmatrix.sync.aligned.m8n8.x4.shared.b16 {%0,%1,%2,%3}, [%4];"
        : "=r"(r[0]), "=r"(r[1]), "=r"(r[2]), "=r"(r[3]) : "r"(a));
}
__device__ __forceinline__ void mma16816(float* c, const uint32_t* a, const uint32_t* b) {
    asm volatile(
        "mma.sync.aligned.m16n8k16.row.col.f32.f16.f16.f32 "
        "{%0,%1,%2,%3}, {%4,%5,%6,%7}, {%8,%9}, {%0,%1,%2,%3};"
        : "+f"(c[0]), "+f"(c[1]), "+f"(c[2]), "+f"(c[3])
        : "r"(a[0]), "r"(a[1]), "r"(a[2]), "r"(a[3]), "r"(b[0]), "r"(b[1]));
}

// 128B-row SW128 swizzle: row r, 16B-chunk q (0..7) -> byte offset in tile
#define SWZ(r, q) ((uint32_t)((r) * 128 + ((((q) ^ ((r) & 7))) << 4)))

// fp16 hi/lo split (hi+lo covers ~22 mantissa bits of the fp32 value)
__device__ __forceinline__ void hsplit(float v, __half& h, __half& l) {
    h = __float2half_rn(v);
    l = __float2half_rn(v - __half2float(h));
}

// ---------------------------------------------------------------------------
// Scratch (device globals)
// ---------------------------------------------------------------------------
__device__ __half g_xhi   [BATCH * SEQ * EMBED];
__device__ __half g_xlo   [BATCH * SEQ * EMBED];
__device__ __half g_xThi  [BATCH * EMBED * SEQ];
__device__ float  g_scores[BATCH * SEQ * SEQ];
__device__ __half g_whi   [BATCH * SEQ * SEQ];
__device__ __half g_atthi [BATCH * SEQ * EMBED];
__device__ __half g_hidhi [BATCH * SEQ * HID];
__device__ __half g_W1t   [HID * EMBED];
__device__ __half g_W2t   [(size_t)VOCAB * HID];

// ---------------------------------------------------------------------------
// Merged embedding gather + split + transpose.
// One pass over emb produces xhi, xlo (row-major [S,E]) and xThi ([E,S]).
// Block (8,32): 32x32 fp32 tile, float4 loads, conflict-free smem transpose.
// ---------------------------------------------------------------------------
__global__ void embed_xt_kernel(const int* __restrict__ ids, const float* __restrict__ emb,
                                __half* __restrict__ xhi, __half* __restrict__ xlo,
                                __half* __restrict__ xThi) {
    __shared__ float t[32][33];
    long z = blockIdx.z;
    const int* idz = ids + z * SEQ;
    xhi  += z * (long)SEQ * EMBED;
    xlo  += z * (long)SEQ * EMBED;
    xThi += z * (long)EMBED * SEQ;
    int c0 = blockIdx.x * 32;   // embed dims
    int r0 = blockIdx.y * 32;   // tokens
    int tx = threadIdx.x;       // 0..7
    int ty = threadIdx.y;       // 0..31

    int id = idz[r0 + ty];
    float4 v = *reinterpret_cast<const float4*>(emb + (long)id * EMBED + c0 + 4 * tx);

    // row-major hi/lo
    __half h0, l0, h1, l1, h2, l2, h3, l3;
    hsplit(v.x, h0, l0); hsplit(v.y, h1, l1); hsplit(v.z, h2, l2); hsplit(v.w, h3, l3);
    {
        long o = (long)(r0 + ty) * EMBED + c0 + 4 * tx;
        __half2 ph0 = __halves2half2(h0, h1), ph1 = __halves2half2(h2, h3);
        __half2 pl0 = __halves2half2(l0, l1), pl1 = __halves2half2(l2, l3);
        uint2 uh, ul;
        uh.x = *reinterpret_cast<uint32_t*>(&ph0); uh.y = *reinterpret_cast<uint32_t*>(&ph1);
        ul.x = *reinterpret_cast<uint32_t*>(&pl0); ul.y = *reinterpret_cast<uint32_t*>(&pl1);
        *reinterpret_cast<uint2*>(xhi + o) = uh;
        *reinterpret_cast<uint2*>(xlo + o) = ul;
    }

    // stage for transpose
    t[ty][4 * tx + 0] = v.x;
    t[ty][4 * tx + 1] = v.y;
    t[ty][4 * tx + 2] = v.z;
    t[ty][4 * tx + 3] = v.w;
    __syncthreads();

    // transposed: xThi[(c0+ty)][r0 + 4tx .. +3]
    {
        __half2 p0 = __halves2half2(__float2half_rn(t[4 * tx + 0][ty]),
                                    __float2half_rn(t[4 * tx + 1][ty]));
        __half2 p1 = __halves2half2(__float2half_rn(t[4 * tx + 2][ty]),
                                    __float2half_rn(t[4 * tx + 3][ty]));
        uint2 o;
        o.x = *reinterpret_cast<uint32_t*>(&p0);
        o.y = *reinterpret_cast<uint32_t*>(&p1);
        *reinterpret_cast<uint2*>(xThi + (long)(c0 + ty) * SEQ + r0 + 4 * tx) = o;
    }
}

// ---------------------------------------------------------------------------
// Combined weight transpose (float4): z=0 W1 [E,H]->[H,E], z=1 W2 [H,V]->[V,H]
// Block (8,32), 32x32 tiles, conflict-free.
// ---------------------------------------------------------------------------
__global__ void transpose_weights_kernel(const float* __restrict__ W1,
                                         const float* __restrict__ W2,
                                         __half* __restrict__ w1t,
                                         __half* __restrict__ w2t) {
    __shared__ float t[32][33];
    const float* in; __half* outp; int R, C;
    if (blockIdx.z == 0) {
        if (blockIdx.x >= HID / 32 || blockIdx.y >= EMBED / 32) return;
        in = W1; outp = w1t; R = EMBED; C = HID;
    } else {
        in = W2; outp = w2t; R = HID; C = VOCAB;
    }
    int c0 = blockIdx.x * 32, r0 = blockIdx.y * 32;
    int tx = threadIdx.x, ty = threadIdx.y;

    float4 v = *reinterpret_cast<const float4*>(in + (long)(r0 + ty) * C + c0 + 4 * tx);
    t[ty][4 * tx + 0] = v.x;
    t[ty][4 * tx + 1] = v.y;
    t[ty][4 * tx + 2] = v.z;
    t[ty][4 * tx + 3] = v.w;
    __syncthreads();

    __half2 p0 = __halves2half2(__float2half_rn(t[4 * tx + 0][ty]),
                                __float2half_rn(t[4 * tx + 1][ty]));
    __half2 p1 = __halves2half2(__float2half_rn(t[4 * tx + 2][ty]),
                                __float2half_rn(t[4 * tx + 3][ty]));
    uint2 o;
    o.x = *reinterpret_cast<uint32_t*>(&p0);
    o.y = *reinterpret_cast<uint32_t*>(&p1);
    *reinterpret_cast<uint2*>(outp + (long)(c0 + ty) * R + r0 + 4 * tx) = o;
}

// ---------------------------------------------------------------------------
// Softmax rows (fp32 in) -> fp16 hi weights only
// ---------------------------------------------------------------------------
__global__ __launch_bounds__(256)
void softmax_kernel(const float* __restrict__ scores, __half* __restrict__ whi) {
    __shared__ float red[256];
    const float* row = scores + (long)blockIdx.x * SEQ;
    __half* oh = whi + (long)blockIdx.x * SEQ;
    const int tid = threadIdx.x;

    float v[8];
    float lmax = -3.402823466e+38f;
    #pragma unroll
    for (int i = 0; i < 8; i++) { v[i] = row[tid + i * 256]; lmax = fmaxf(lmax, v[i]); }
    red[tid] = lmax; __syncthreads();
    #pragma unroll
    for (int s = 128; s > 0; s >>= 1) { if (tid < s) red[tid] = fmaxf(red[tid], red[tid + s]); __syncthreads(); }
    float m = red[0]; __syncthreads();

    float lsum = 0.f;
    #pragma unroll
    for (int i = 0; i < 8; i++) { v[i] = __expf(v[i] - m); lsum += v[i]; }
    red[tid] = lsum; __syncthreads();
    #pragma unroll
    for (int s = 128; s > 0; s >>= 1) { if (tid < s) red[tid] += red[tid + s]; __syncthreads(); }
    float inv = 1.f / red[0];
    #pragma unroll
    for (int i = 0; i < 8; i++)
        oh[tid + i * 256] = __float2half_rn(v[i] * inv);
}

// ---------------------------------------------------------------------------
// 3-term split-fp16 symmetric GEMM (scores):  C = A*A^T, upper-tri + mirror.
// CTA 128x128, BK=64, 8 warps, 3 stages. (R12 champion configuration.)
// ---------------------------------------------------------------------------
#define BMT 128
#define BKT 64
#define TILE_BYTES 16384    // 128 rows x 128 B

__device__ __forceinline__ void load_chunk_sym(uint32_t sbase, int st,
    const __half* __restrict__ gA0, const __half* __restrict__ gA1,
    const __half* __restrict__ gB0, const __half* __restrict__ gB1,
    int K, int k0, int tid)
{
    uint32_t s0 = sbase + (uint32_t)(st * 4 * TILE_BYTES);
    #pragma unroll
    for (int it = 0; it < 4; it++) {
        int idx = tid + it * 256;
        int r = idx >> 3, c = idx & 7;
        uint32_t so = SWZ(r, c);
        long go = (long)r * K + k0 + c * 8;
        CP_ASYNC16(s0 + 0 * TILE_BYTES + so, gA0 + go);
        CP_ASYNC16(s0 + 1 * TILE_BYTES + so, gA1 + go);
        CP_ASYNC16(s0 + 2 * TILE_BYTES + so, gB0 + go);
        CP_ASYNC16(s0 + 3 * TILE_BYTES + so, gB1 + go);
    }
}

__global__ __launch_bounds__(256, 1)
void hgemm_sym(const __half* __restrict__ A0, const __half* __restrict__ A1,
               float* __restrict__ Cf, int N, int K, long sA, long sC, int ntm)
{
    extern __shared__ char smem[];
    const uint32_t sbase = smem_u32(smem);
    const int tid  = threadIdx.x;
    const int wid  = tid >> 5, lane = tid & 31;
    const int wm   = wid & 1,  wn   = wid >> 1;

    int t0 = blockIdx.x, i0 = 0;
    while (t0 >= ntm - i0) { t0 -= ntm - i0; i0++; }
    int pm = i0, pn = i0 + t0;
    long m0 = (long)pm * BMT, n0 = (long)pn * BMT;
    long zb = blockIdx.z;
    const __half* gA0 = A0 + zb * sA + m0 * K;
    const __half* gA1 = A1 + zb * sA + m0 * K;
    const __half* gB0 = A0 + zb * sA + n0 * K;
    const __half* gB1 = A1 + zb * sA + n0 * K;

    float acc[4][4][4];
    #pragma unroll
    for (int i = 0; i < 4; i++)
        #pragma unroll
        for (int j = 0; j < 4; j++)
            #pragma unroll
            for (int k = 0; k < 4; k++) acc[i][j][k] = 0.f;

    const int ar = lane & 15;
    const int ak = (lane >> 4) << 3;
    const int br = ((lane >> 4) << 3) + (lane & 7);
    const int bk = ((lane >> 3) & 1) << 3;

    load_chunk_sym(sbase, 0, gA0, gA1, gB0, gB1, K, 0, tid);   CP_COMMIT();
    load_chunk_sym(sbase, 1, gA0, gA1, gB0, gB1, K, BKT, tid); CP_COMMIT();

    const int nc = K / BKT;
    for (int c = 0; c < nc; c++) {
        CP_WAIT1();
        __syncthreads();
        if (c + 2 < nc)
            load_chunk_sym(sbase, (c + 2) % 3, gA0, gA1, gB0, gB1, K, (c + 2) * BKT, tid);
        CP_COMMIT();

        uint32_t s0 = sbase + (uint32_t)((c % 3) * 4 * TILE_BYTES);
        #pragma unroll
        for (int kb = 0; kb < BKT; kb += 16) {
            uint32_t a0f[4][4], a1f[4][4], b0f[2][4], b1f[2][4];
            int aq = (kb + ak) >> 3;
            int bq = (kb + bk) >> 3;
            #pragma unroll
            for (int mt = 0; mt < 4; mt++) {
                int r = wm * 64 + mt * 16 + ar;
                uint32_t ad = s0 + SWZ(r, aq);
                ldsm4(a0f[mt], ad);
                ldsm4(a1f[mt], ad + TILE_BYTES);
            }
            #pragma unroll
            for (int nt = 0; nt < 2; nt++) {
                int r = wn * 32 + nt * 16 + br;
                uint32_t bd = s0 + 2 * TILE_BYTES + SWZ(r, bq);
                ldsm4(b0f[nt], bd);
                ldsm4(b1f[nt], bd + TILE_BYTES);
            }
            #pragma unroll
            for (int mt = 0; mt < 4; mt++)
                #pragma unroll
                for (int n8 = 0; n8 < 4; n8++) {
                    const uint32_t* b = &b0f[n8 >> 1][(n8 & 1) * 2];
                    mma16816(acc[mt][n8], a0f[mt], b);
                    mma16816(acc[mt][n8], a1f[mt], b);
                    mma16816(acc[mt][n8], a0f[mt], &b1f[n8 >> 1][(n8 & 1) * 2]);
                }
        }
    }

    // ---- epilogue (direct tile) ----
    long zC = zb * sC;
    int rb = lane >> 2;
    int cb = (lane & 3) * 2;
    #pragma unroll
    for (int mt = 0; mt < 4; mt++) {
        #pragma unroll
        for (int n8 = 0; n8 < 4; n8++) {
            long col = n0 + wn * 32 + n8 * 8 + cb;
            #pragma unroll
            for (int h = 0; h < 2; h++) {
                long row = m0 + wm * 64 + mt * 16 + rb + h * 8;
                *reinterpret_cast<float2*>(Cf + zC + row * (long)N + col) =
                    make_float2(acc[mt][n8][h * 2 + 0], acc[mt][n8][h * 2 + 1]);
            }
        }
    }

    // ---- mirror transposed tile at (pn, pm) ----
    if (pm != pn) {
        __syncthreads();
        float* stg = reinterpret_cast<float*>(smem);   // 128 x 129 floats
        #pragma unroll
        for (int mt = 0; mt < 4; mt++)
            #pragma unroll
            for (int n8 = 0; n8 < 4; n8++) {
                int colb = wn * 32 + n8 * 8 + cb;
                #pragma unroll
                for (int h = 0; h < 2; h++) {
                    int rowb = wm * 64 + mt * 16 + rb + h * 8;
                    stg[rowb * 129 + colb]     = acc[mt][n8][h * 2 + 0];
                    stg[rowb * 129 + colb + 1] = acc[mt][n8][h * 2 + 1];
                }
            }
        __syncthreads();
        #pragma unroll
        for (int it = 0; it < 64; it++) {
            int idx = tid + it * 256;
            int rr = idx >> 7, cc = idx & 127;
            Cf[zC + (n0 + rr) * (long)N + m0 + cc] = stg[cc * 129 + rr];
        }
    }
}

// ---------------------------------------------------------------------------
// 1-term HMMA GEMM (attended, FFN1, FFN2): 2 CTAs/SM, CTA 128x128, BK=64,
// 8 warps, 3 stages (96 KB/CTA).  OUT=0: fp32.  OUT=1: fp16 hi.  Batched via z.
// ---------------------------------------------------------------------------
#define F2_STAGE (2 * TILE_BYTES)      // A tile + B tile = 32 KB
#define F2_SMEM  (3 * F2_STAGE)        // 98304

__device__ __forceinline__ void load_chunk_1t(uint32_t sbase, int st,
    const __half* __restrict__ gA, const __half* __restrict__ gB,
    int K, int k0, int tid)
{
    uint32_t s0 = sbase + (uint32_t)(st * F2_STAGE);
    #pragma unroll
    for (int it = 0; it < 4; it++) {
        int idx = tid + it * 256;
        int r = idx >> 3, c = idx & 7;
        uint32_t so = SWZ(r, c);
        long go = (long)r * K + k0 + c * 8;
        CP_ASYNC16(s0 + so, gA + go);
        CP_ASYNC16(s0 + TILE_BYTES + so, gB + go);
    }
}

template<int OUT, bool BIAS, bool RELU>
__global__ __launch_bounds__(256, 2)
void hgemm_1t(const __half* __restrict__ A0, const __half* __restrict__ B0,
              const float* __restrict__ bias,
              float* __restrict__ Cf, __half* __restrict__ Chi,
              int M, int N, int K, long sA, long sB, long sC, int ntm)
{
    extern __shared__ char smem[];
    const uint32_t sbase = smem_u32(smem);
    const int tid  = threadIdx.x;
    const int wid  = tid >> 5, lane = tid & 31;
    const int wm   = wid & 1,  wn   = wid >> 1;

    int pm = blockIdx.x % ntm, pn = blockIdx.x / ntm;
    long m0 = (long)pm * 128, n0 = (long)pn * 128;
    long zb = blockIdx.z;
    const __half* gA = A0 + zb * sA + m0 * K;
    const __half* gB = B0 + zb * sB + n0 * K;

    float acc[4][4][4];
    #pragma unroll
    for (int i = 0; i < 4; i++)
        #pragma unroll
        for (int j = 0; j < 4; j++)
            #pragma unroll
            for (int k = 0; k < 4; k++) acc[i][j][k] = 0.f;

    const int ar = lane & 15;
    const int ak = (lane >> 4) << 3;
    const int br = ((lane >> 4) << 3) + (lane & 7);
    const int bk = ((lane >> 3) & 1) << 3;

    load_chunk_1t(sbase, 0, gA, gB, K, 0, tid);    CP_COMMIT();
    load_chunk_1t(sbase, 1, gA, gB, K, BKT, tid);  CP_COMMIT();

    const int nc = K / BKT;
    for (int c = 0; c < nc; c++) {
        CP_WAIT1();
        __syncthreads();
        if (c + 2 < nc)
            load_chunk_1t(sbase, (c + 2) % 3, gA, gB, K, (c + 2) * BKT, tid);
        CP_COMMIT();

        uint32_t s0 = sbase + (uint32_t)((c % 3) * F2_STAGE);
        #pragma unroll
        for (int kb = 0; kb < BKT; kb += 16) {
            uint32_t af[4][4], bf[2][4];
            int aq = (kb + ak) >> 3;
            int bq = (kb + bk) >> 3;
            #pragma unroll
            for (int mt = 0; mt < 4; mt++) {
                int r = wm * 64 + mt * 16 + ar;
                ldsm4(af[mt], s0 + SWZ(r, aq));
            }
            #pragma unroll
            for (int nt = 0; nt < 2; nt++) {
                int r = wn * 32 + nt * 16 + br;
                ldsm4(bf[nt], s0 + TILE_BYTES + SWZ(r, bq));
            }
            #pragma unroll
            for (int mt = 0; mt < 4; mt++)
                #pragma unroll
                for (int n8 = 0; n8 < 4; n8++)
                    mma16816(acc[mt][n8], af[mt], &bf[n8 >> 1][(n8 & 1) * 2]);
        }
    }

    // ---- epilogue ----
    long zC = zb * sC;
    int rb = lane >> 2;
    int cb = (lane & 3) * 2;
    #pragma unroll
    for (int mt = 0; mt < 4; mt++) {
        #pragma unroll
        for (int n8 = 0; n8 < 4; n8++) {
            long col = n0 + wn * 32 + n8 * 8 + cb;
            float bv0 = 0.f, bv1 = 0.f;
            if (BIAS) { bv0 = bias[col]; bv1 = bias[col + 1]; }
            #pragma unroll
            for (int h = 0; h < 2; h++) {
                long row = m0 + wm * 64 + mt * 16 + rb + h * 8;
                float v0 = acc[mt][n8][h * 2 + 0] + bv0;
                float v1 = acc[mt][n8][h * 2 + 1] + bv1;
                if (RELU) { v0 = fmaxf(v0, 0.f); v1 = fmaxf(v1, 0.f); }
                long o = row * (long)N + col;
                if (OUT == 0) {
                    *reinterpret_cast<float2*>(Cf + zC + o) = make_float2(v0, v1);
                } else {
                    *reinterpret_cast<__half2*>(Chi + zC + o) =
                        __halves2half2(__float2half_rn(v0), __float2half_rn(v1));
                }
            }
        }
    }
}

// ---------------------------------------------------------------------------
// Launch
// ---------------------------------------------------------------------------
extern "C" void kernel_launch(void* const* d_in, const int* in_sizes, int n_in,
                              void* d_out, int out_size) {
    const int*   ids = (const int*)  d_in[0];
    const float* emb = (const float*)d_in[1];
    const float* W1  = (const float*)d_in[2];
    const float* b1  = (const float*)d_in[3];
    const float* W2  = (const float*)d_in[4];
    const float* b2  = (const float*)d_in[5];
    float* out = (float*)d_out;

    float* scores;
    __half *xhi, *xlo, *xThi, *whi, *athi, *hdhi, *w1t, *w2t;
    cudaGetSymbolAddress((void**)&scores, g_scores);
    cudaGetSymbolAddress((void**)&xhi,    g_xhi);
    cudaGetSymbolAddress((void**)&xlo,    g_xlo);
    cudaGetSymbolAddress((void**)&xThi,   g_xThi);
    cudaGetSymbolAddress((void**)&whi,    g_whi);
    cudaGetSymbolAddress((void**)&athi,   g_atthi);
    cudaGetSymbolAddress((void**)&hdhi,   g_hidhi);
    cudaGetSymbolAddress((void**)&w1t,    g_W1t);
    cudaGetSymbolAddress((void**)&w2t,    g_W2t);

    const int SM3 = 4 * 3 * TILE_BYTES;   // scores: 196608
    cudaFuncSetAttribute(hgemm_sym, cudaFuncAttributeMaxDynamicSharedMemorySize, SM3);
    cudaFuncSetAttribute(hgemm_1t<1, false, false>, cudaFuncAttributeMaxDynamicSharedMemorySize, F2_SMEM);
    cudaFuncSetAttribute(hgemm_1t<1, true,  true >, cudaFuncAttributeMaxDynamicSharedMemorySize, F2_SMEM);
    cudaFuncSetAttribute(hgemm_1t<0, true,  false>, cudaFuncAttributeMaxDynamicSharedMemorySize, F2_SMEM);

    // 0) embedding -> xhi, xlo, xThi in one gather pass
    {
        dim3 grid(EMBED / 32, SEQ / 32, BATCH);
        embed_xt_kernel<<<grid, dim3(8, 32)>>>(ids, emb, xhi, xlo, xThi);
    }
    // 1) W1t + W2t single fp16 (combined, float4)
    {
        dim3 grid(VOCAB / 32, HID / 32, 2);
        transpose_weights_kernel<<<grid, dim3(8, 32)>>>(W1, W2, w1t, w2t);
    }

    // 2) scores = x @ x^T  (3-term symmetric, upper-tri + mirror)  M=N=2048 K=1024
    {
        const int ntm = SEQ / BMT;                 // 16
        dim3 grid(ntm * (ntm + 1) / 2, 1, BATCH);  // 136 x 4
        hgemm_sym<<<grid, 256, SM3>>>(
            xhi, xlo, scores, SEQ, EMBED, (long)SEQ * EMBED, (long)SEQ * SEQ, ntm);
    }

    // 3) softmax -> w hi
    softmax_kernel<<<BATCH * SEQ, 256>>>(scores, whi);

    // 4) attended = w @ x  (1-term NT, 2CTA/SM, fp16 hi out)  M=2048 N=1024 K=2048
    {
        dim3 grid((SEQ / 128) * (EMBED / 128), 1, BATCH);
        hgemm_1t<1, false, false><<<grid, 256, F2_SMEM>>>(
            whi, xThi, nullptr, nullptr, athi,
            SEQ, EMBED, SEQ,
            (long)SEQ * SEQ, (long)EMBED * SEQ, (long)SEQ * EMBED,
            SEQ / 128);
    }

    // 5) hidden = relu(att @ W1 + b1)  (1-term NT, 2CTA/SM, fp16 hi out)  M=8192 N=4096 K=1024
    {
        dim3 grid(((BATCH * SEQ) / 128) * (HID / 128), 1, 1);
        hgemm_1t<1, true, true><<<grid, 256, F2_SMEM>>>(
            athi, w1t, b1, nullptr, hdhi,
            BATCH * SEQ, HID, EMBED, 0, 0, 0,
            (BATCH * SEQ) / 128);
    }

    // 6) logits = hidden @ W2 + b2  (1-term NT, 2CTA/SM, fp32 out)  M=8192 N=32000 K=4096
    {
        dim3 grid(((BATCH * SEQ) / 128) * (VOCAB / 128), 1, 1);
        hgemm_1t<0, true, false><<<grid, 256, F2_SMEM>>>(
            hdhi, w2t, b2, out, nullptr,
            BATCH * SEQ, VOCAB, HID, 0, 0, 0,
            (BATCH * SEQ) / 128);
    }
}

// round 16
// speedup vs baseline: 1.1212x; 1.0125x over previous
#include <cuda_runtime.h>
#include <cuda_fp16.h>
#include <cstdint>

// Problem dims
#define BATCH 4
#define SEQ   2048
#define EMBED 1024
#define HID   4096
#define VOCAB 32000

// ---------------------------------------------------------------------------
// PTX helpers (plain sm_103-legal: cp.async / ldmatrix / mma.sync only)
// ---------------------------------------------------------------------------
__device__ __forceinline__ uint32_t smem_u32(const void* p) {
    uint32_t a;
    asm("{ .reg .u64 t; cvta.to.shared.u64 t, %1; cvt.u32.u64 %0, t; }" : "=r"(a) : "l"(p));
    return a;
}
#define CP_ASYNC16(s, g) \
    asm volatile("cp.async.cg.shared.global [%0], [%1], 16;\n" :: "r"(s), "l"(g))
#define CP_COMMIT() asm volatile("cp.async.commit_group;\n" ::: "memory")
#define CP_WAIT1()  asm volatile("cp.async.wait_group 1;\n" ::: "memory")

__device__ __forceinline__ void ldsm4(uint32_t* r, uint32_t a) {
    asm volatile("ldmatrix.sync.aligned.m8n8.x4.shared.b16 {%0,%1,%2,%3}, [%4];"
        : "=r"(r[0]), "=r"(r[1]), "=r"(r[2]), "=r"(r[3]) : "r"(a));
}
__device__ __forceinline__ void mma16816(float* c, const uint32_t* a, const uint32_t* b) {
    asm volatile(
        "mma.sync.aligned.m16n8k16.row.col.f32.f16.f16.f32 "
        "{%0,%1,%2,%3}, {%4,%5,%6,%7}, {%8,%9}, {%0,%1,%2,%3};"
        : "+f"(c[0]), "+f"(c[1]), "+f"(c[2]), "+f"(c[3])
        : "r"(a[0]), "r"(a[1]), "r"(a[2]), "r"(a[3]), "r"(b[0]), "r"(b[1]));
}

// 128B-row SW128 swizzle: row r, 16B-chunk q (0..7) -> byte offset in tile
#define SWZ(r, q) ((uint32_t)((r) * 128 + ((((q) ^ ((r) & 7))) << 4)))

// fp16 hi/lo split (hi+lo covers ~22 mantissa bits of the fp32 value)
__device__ __forceinline__ void hsplit(float v, __half& h, __half& l) {
    h = __float2half_rn(v);
    l = __float2half_rn(v - __half2float(h));
}

// ---------------------------------------------------------------------------
// Scratch (device globals)
// ---------------------------------------------------------------------------
__device__ __half g_xhi   [BATCH * SEQ * EMBED];
__device__ __half g_xlo   [BATCH * SEQ * EMBED];
__device__ __half g_xThi  [BATCH * EMBED * SEQ];
__device__ float  g_scores[BATCH * SEQ * SEQ];
__device__ __half g_whi   [BATCH * SEQ * SEQ];
__device__ __half g_atthi [BATCH * SEQ * EMBED];
__device__ __half g_hidhi [BATCH * SEQ * HID];
__device__ __half g_W1t   [HID * EMBED];
__device__ __half g_W2t   [(size_t)VOCAB * HID];

// ---------------------------------------------------------------------------
// Merged embedding gather + split + transpose.
// ---------------------------------------------------------------------------
__global__ void embed_xt_kernel(const int* __restrict__ ids, const float* __restrict__ emb,
                                __half* __restrict__ xhi, __half* __restrict__ xlo,
                                __half* __restrict__ xThi) {
    __shared__ float t[32][33];
    long z = blockIdx.z;
    const int* idz = ids + z * SEQ;
    xhi  += z * (long)SEQ * EMBED;
    xlo  += z * (long)SEQ * EMBED;
    xThi += z * (long)EMBED * SEQ;
    int c0 = blockIdx.x * 32;
    int r0 = blockIdx.y * 32;
    int tx = threadIdx.x;       // 0..7
    int ty = threadIdx.y;       // 0..31

    int id = idz[r0 + ty];
    float4 v = *reinterpret_cast<const float4*>(emb + (long)id * EMBED + c0 + 4 * tx);

    __half h0, l0, h1, l1, h2, l2, h3, l3;
    hsplit(v.x, h0, l0); hsplit(v.y, h1, l1); hsplit(v.z, h2, l2); hsplit(v.w, h3, l3);
    {
        long o = (long)(r0 + ty) * EMBED + c0 + 4 * tx;
        __half2 ph0 = __halves2half2(h0, h1), ph1 = __halves2half2(h2, h3);
        __half2 pl0 = __halves2half2(l0, l1), pl1 = __halves2half2(l2, l3);
        uint2 uh, ul;
        uh.x = *reinterpret_cast<uint32_t*>(&ph0); uh.y = *reinterpret_cast<uint32_t*>(&ph1);
        ul.x = *reinterpret_cast<uint32_t*>(&pl0); ul.y = *reinterpret_cast<uint32_t*>(&pl1);
        *reinterpret_cast<uint2*>(xhi + o) = uh;
        *reinterpret_cast<uint2*>(xlo + o) = ul;
    }

    t[ty][4 * tx + 0] = v.x;
    t[ty][4 * tx + 1] = v.y;
    t[ty][4 * tx + 2] = v.z;
    t[ty][4 * tx + 3] = v.w;
    __syncthreads();

    {
        __half2 p0 = __halves2half2(__float2half_rn(t[4 * tx + 0][ty]),
                                    __float2half_rn(t[4 * tx + 1][ty]));
        __half2 p1 = __halves2half2(__float2half_rn(t[4 * tx + 2][ty]),
                                    __float2half_rn(t[4 * tx + 3][ty]));
        uint2 o;
        o.x = *reinterpret_cast<uint32_t*>(&p0);
        o.y = *reinterpret_cast<uint32_t*>(&p1);
        *reinterpret_cast<uint2*>(xThi + (long)(c0 + ty) * SEQ + r0 + 4 * tx) = o;
    }
}

// ---------------------------------------------------------------------------
// Combined weight transpose (float4, FLAT grid — no empty blocks):
// tiles [0, NT1) -> W1 [E,H]->[H,E]; tiles [NT1, NT1+NT2) -> W2 [H,V]->[V,H]
// ---------------------------------------------------------------------------
#define NT1 ((EMBED / 32) * (HID / 32))     // 4096
#define NT2 ((HID / 32) * (VOCAB / 32))     // 128000

__global__ void transpose_weights_kernel(const float* __restrict__ W1,
                                         const float* __restrict__ W2,
                                         __half* __restrict__ w1t,
                                         __half* __restrict__ w2t) {
    __shared__ float t[32][33];
    int T = blockIdx.x;
    const float* in; __half* outp; int R, C, tr, tc;
    if (T < NT1) {
        in = W1; outp = w1t; R = EMBED; C = HID;
        tr = T / (HID / 32); tc = T % (HID / 32);
    } else {
        T -= NT1;
        in = W2; outp = w2t; R = HID; C = VOCAB;
        tr = T / (VOCAB / 32); tc = T % (VOCAB / 32);
    }
    int c0 = tc * 32, r0 = tr * 32;
    int tx = threadIdx.x, ty = threadIdx.y;

    float4 v = *reinterpret_cast<const float4*>(in + (long)(r0 + ty) * C + c0 + 4 * tx);
    t[ty][4 * tx + 0] = v.x;
    t[ty][4 * tx + 1] = v.y;
    t[ty][4 * tx + 2] = v.z;
    t[ty][4 * tx + 3] = v.w;
    __syncthreads();

    __half2 p0 = __halves2half2(__float2half_rn(t[4 * tx + 0][ty]),
                                __float2half_rn(t[4 * tx + 1][ty]));
    __half2 p1 = __halves2half2(__float2half_rn(t[4 * tx + 2][ty]),
                                __float2half_rn(t[4 * tx + 3][ty]));
    uint2 o;
    o.x = *reinterpret_cast<uint32_t*>(&p0);
    o.y = *reinterpret_cast<uint32_t*>(&p1);
    *reinterpret_cast<uint2*>(outp + (long)(c0 + ty) * R + r0 + 4 * tx) = o;
}

// ---------------------------------------------------------------------------
// Softmax rows (fp32 in) -> fp16 hi weights only
// ---------------------------------------------------------------------------
__global__ __launch_bounds__(256)
void softmax_kernel(const float* __restrict__ scores, __half* __restrict__ whi) {
    __shared__ float red[256];
    const float* row = scores + (long)blockIdx.x * SEQ;
    __half* oh = whi + (long)blockIdx.x * SEQ;
    const int tid = threadIdx.x;

    float v[8];
    float lmax = -3.402823466e+38f;
    #pragma unroll
    for (int i = 0; i < 8; i++) { v[i] = row[tid + i * 256]; lmax = fmaxf(lmax, v[i]); }
    red[tid] = lmax; __syncthreads();
    #pragma unroll
    for (int s = 128; s > 0; s >>= 1) { if (tid < s) red[tid] = fmaxf(red[tid], red[tid + s]); __syncthreads(); }
    float m = red[0]; __syncthreads();

    float lsum = 0.f;
    #pragma unroll
    for (int i = 0; i < 8; i++) { v[i] = __expf(v[i] - m); lsum += v[i]; }
    red[tid] = lsum; __syncthreads();
    #pragma unroll
    for (int s = 128; s > 0; s >>= 1) { if (tid < s) red[tid] += red[tid + s]; __syncthreads(); }
    float inv = 1.f / red[0];
    #pragma unroll
    for (int i = 0; i < 8; i++)
        oh[tid + i * 256] = __float2half_rn(v[i] * inv);
}

// ---------------------------------------------------------------------------
// 3-term split-fp16 symmetric GEMM (scores):  C = A*A^T, upper-tri + mirror.
// CTA 128x128, BK=64, 8 warps, 3 stages. (Champion configuration.)
// ---------------------------------------------------------------------------
#define BMT 128
#define BKT 64
#define TILE_BYTES 16384    // 128 rows x 128 B

__device__ __forceinline__ void load_chunk_sym(uint32_t sbase, int st,
    const __half* __restrict__ gA0, const __half* __restrict__ gA1,
    const __half* __restrict__ gB0, const __half* __restrict__ gB1,
    int K, int k0, int tid)
{
    uint32_t s0 = sbase + (uint32_t)(st * 4 * TILE_BYTES);
    #pragma unroll
    for (int it = 0; it < 4; it++) {
        int idx = tid + it * 256;
        int r = idx >> 3, c = idx & 7;
        uint32_t so = SWZ(r, c);
        long go = (long)r * K + k0 + c * 8;
        CP_ASYNC16(s0 + 0 * TILE_BYTES + so, gA0 + go);
        CP_ASYNC16(s0 + 1 * TILE_BYTES + so, gA1 + go);
        CP_ASYNC16(s0 + 2 * TILE_BYTES + so, gB0 + go);
        CP_ASYNC16(s0 + 3 * TILE_BYTES + so, gB1 + go);
    }
}

__global__ __launch_bounds__(256, 1)
void hgemm_sym(const __half* __restrict__ A0, const __half* __restrict__ A1,
               float* __restrict__ Cf, int N, int K, long sA, long sC, int ntm)
{
    extern __shared__ char smem[];
    const uint32_t sbase = smem_u32(smem);
    const int tid  = threadIdx.x;
    const int wid  = tid >> 5, lane = tid & 31;
    const int wm   = wid & 1,  wn   = wid >> 1;

    int t0 = blockIdx.x, i0 = 0;
    while (t0 >= ntm - i0) { t0 -= ntm - i0; i0++; }
    int pm = i0, pn = i0 + t0;
    long m0 = (long)pm * BMT, n0 = (long)pn * BMT;
    long zb = blockIdx.z;
    const __half* gA0 = A0 + zb * sA + m0 * K;
    const __half* gA1 = A1 + zb * sA + m0 * K;
    const __half* gB0 = A0 + zb * sA + n0 * K;
    const __half* gB1 = A1 + zb * sA + n0 * K;

    float acc[4][4][4];
    #pragma unroll
    for (int i = 0; i < 4; i++)
        #pragma unroll
        for (int j = 0; j < 4; j++)
            #pragma unroll
            for (int k = 0; k < 4; k++) acc[i][j][k] = 0.f;

    const int ar = lane & 15;
    const int ak = (lane >> 4) << 3;
    const int br = ((lane >> 4) << 3) + (lane & 7);
    const int bk = ((lane >> 3) & 1) << 3;

    load_chunk_sym(sbase, 0, gA0, gA1, gB0, gB1, K, 0, tid);   CP_COMMIT();
    load_chunk_sym(sbase, 1, gA0, gA1, gB0, gB1, K, BKT, tid); CP_COMMIT();

    const int nc = K / BKT;
    for (int c = 0; c < nc; c++) {
        CP_WAIT1();
        __syncthreads();
        if (c + 2 < nc)
            load_chunk_sym(sbase, (c + 2) % 3, gA0, gA1, gB0, gB1, K, (c + 2) * BKT, tid);
        CP_COMMIT();

        uint32_t s0 = sbase + (uint32_t)((c % 3) * 4 * TILE_BYTES);
        #pragma unroll
        for (int kb = 0; kb < BKT; kb += 16) {
            uint32_t a0f[4][4], a1f[4][4], b0f[2][4], b1f[2][4];
            int aq = (kb + ak) >> 3;
            int bq = (kb + bk) >> 3;
            #pragma unroll
            for (int mt = 0; mt < 4; mt++) {
                int r = wm * 64 + mt * 16 + ar;
                uint32_t ad = s0 + SWZ(r, aq);
                ldsm4(a0f[mt], ad);
                ldsm4(a1f[mt], ad + TILE_BYTES);
            }
            #pragma unroll
            for (int nt = 0; nt < 2; nt++) {
                int r = wn * 32 + nt * 16 + br;
                uint32_t bd = s0 + 2 * TILE_BYTES + SWZ(r, bq);
                ldsm4(b0f[nt], bd);
                ldsm4(b1f[nt], bd + TILE_BYTES);
            }
            #pragma unroll
            for (int mt = 0; mt < 4; mt++)
                #pragma unroll
                for (int n8 = 0; n8 < 4; n8++) {
                    const uint32_t* b = &b0f[n8 >> 1][(n8 & 1) * 2];
                    mma16816(acc[mt][n8], a0f[mt], b);
                    mma16816(acc[mt][n8], a1f[mt], b);
                    mma16816(acc[mt][n8], a0f[mt], &b1f[n8 >> 1][(n8 & 1) * 2]);
                }
        }
    }

    // ---- epilogue (direct tile) ----
    long zC = zb * sC;
    int rb = lane >> 2;
    int cb = (lane & 3) * 2;
    #pragma unroll
    for (int mt = 0; mt < 4; mt++) {
        #pragma unroll
        for (int n8 = 0; n8 < 4; n8++) {
            long col = n0 + wn * 32 + n8 * 8 + cb;
            #pragma unroll
            for (int h = 0; h < 2; h++) {
                long row = m0 + wm * 64 + mt * 16 + rb + h * 8;
                *reinterpret_cast<float2*>(Cf + zC + row * (long)N + col) =
                    make_float2(acc[mt][n8][h * 2 + 0], acc[mt][n8][h * 2 + 1]);
            }
        }
    }

    // ---- mirror transposed tile at (pn, pm) ----
    if (pm != pn) {
        __syncthreads();
        float* stg = reinterpret_cast<float*>(smem);   // 128 x 129 floats
        #pragma unroll
        for (int mt = 0; mt < 4; mt++)
            #pragma unroll
            for (int n8 = 0; n8 < 4; n8++) {
                int colb = wn * 32 + n8 * 8 + cb;
                #pragma unroll
                for (int h = 0; h < 2; h++) {
                    int rowb = wm * 64 + mt * 16 + rb + h * 8;
                    stg[rowb * 129 + colb]     = acc[mt][n8][h * 2 + 0];
                    stg[rowb * 129 + colb + 1] = acc[mt][n8][h * 2 + 1];
                }
            }
        __syncthreads();
        #pragma unroll
        for (int it = 0; it < 64; it++) {
            int idx = tid + it * 256;
            int rr = idx >> 7, cc = idx & 127;
            Cf[zC + (n0 + rr) * (long)N + m0 + cc] = stg[cc * 129 + rr];
        }
    }
}

// ---------------------------------------------------------------------------
// 1-term HMMA GEMM (attended, FFN1, FFN2): 2 CTAs/SM, CTA 128x128, BK=64,
// 8 warps, 3 stages (96 KB/CTA).  OUT=0: fp32.  OUT=1: fp16 hi.  Batched via z.
// ---------------------------------------------------------------------------
#define F2_STAGE (2 * TILE_BYTES)      // A tile + B tile = 32 KB
#define F2_SMEM  (3 * F2_STAGE)        // 98304

__device__ __forceinline__ void load_chunk_1t(uint32_t sbase, int st,
    const __half* __restrict__ gA, const __half* __restrict__ gB,
    int K, int k0, int tid)
{
    uint32_t s0 = sbase + (uint32_t)(st * F2_STAGE);
    #pragma unroll
    for (int it = 0; it < 4; it++) {
        int idx = tid + it * 256;
        int r = idx >> 3, c = idx & 7;
        uint32_t so = SWZ(r, c);
        long go = (long)r * K + k0 + c * 8;
        CP_ASYNC16(s0 + so, gA + go);
        CP_ASYNC16(s0 + TILE_BYTES + so, gB + go);
    }
}

template<int OUT, bool BIAS, bool RELU>
__global__ __launch_bounds__(256, 2)
void hgemm_1t(const __half* __restrict__ A0, const __half* __restrict__ B0,
              const float* __restrict__ bias,
              float* __restrict__ Cf, __half* __restrict__ Chi,
              int M, int N, int K, long sA, long sB, long sC, int ntm)
{
    extern __shared__ char smem[];
    const uint32_t sbase = smem_u32(smem);
    const int tid  = threadIdx.x;
    const int wid  = tid >> 5, lane = tid & 31;
    const int wm   = wid & 1,  wn   = wid >> 1;

    int pm = blockIdx.x % ntm, pn = blockIdx.x / ntm;
    long m0 = (long)pm * 128, n0 = (long)pn * 128;
    long zb = blockIdx.z;
    const __half* gA = A0 + zb * sA + m0 * K;
    const __half* gB = B0 + zb * sB + n0 * K;

    float acc[4][4][4];
    #pragma unroll
    for (int i = 0; i < 4; i++)
        #pragma unroll
        for (int j = 0; j < 4; j++)
            #pragma unroll
            for (int k = 0; k < 4; k++) acc[i][j][k] = 0.f;

    const int ar = lane & 15;
    const int ak = (lane >> 4) << 3;
    const int br = ((lane >> 4) << 3) + (lane & 7);
    const int bk = ((lane >> 3) & 1) << 3;

    load_chunk_1t(sbase, 0, gA, gB, K, 0, tid);    CP_COMMIT();
    load_chunk_1t(sbase, 1, gA, gB, K, BKT, tid);  CP_COMMIT();

    const int nc = K / BKT;
    for (int c = 0; c < nc; c++) {
        CP_WAIT1();
        __syncthreads();
        if (c + 2 < nc)
            load_chunk_1t(sbase, (c + 2) % 3, gA, gB, K, (c + 2) * BKT, tid);
        CP_COMMIT();

        uint32_t s0 = sbase + (uint32_t)((c % 3) * F2_STAGE);
        #pragma unroll
        for (int kb = 0; kb < BKT; kb += 16) {
            uint32_t af[4][4], bf[2][4];
            int aq = (kb + ak) >> 3;
            int bq = (kb + bk) >> 3;
            #pragma unroll
            for (int mt = 0; mt < 4; mt++) {
                int r = wm * 64 + mt * 16 + ar;
                ldsm4(af[mt], s0 + SWZ(r, aq));
            }
            #pragma unroll
            for (int nt = 0; nt < 2; nt++) {
                int r = wn * 32 + nt * 16 + br;
                ldsm4(bf[nt], s0 + TILE_BYTES + SWZ(r, bq));
            }
            #pragma unroll
            for (int mt = 0; mt < 4; mt++)
                #pragma unroll
                for (int n8 = 0; n8 < 4; n8++)
                    mma16816(acc[mt][n8], af[mt], &bf[n8 >> 1][(n8 & 1) * 2]);
        }
    }

    // ---- epilogue ----
    long zC = zb * sC;
    int rb = lane >> 2;
    int cb = (lane & 3) * 2;
    #pragma unroll
    for (int mt = 0; mt < 4; mt++) {
        #pragma unroll
        for (int n8 = 0; n8 < 4; n8++) {
            long col = n0 + wn * 32 + n8 * 8 + cb;
            float bv0 = 0.f, bv1 = 0.f;
            if (BIAS) { bv0 = bias[col]; bv1 = bias[col + 1]; }
            #pragma unroll
            for (int h = 0; h < 2; h++) {
                long row = m0 + wm * 64 + mt * 16 + rb + h * 8;
                float v0 = acc[mt][n8][h * 2 + 0] + bv0;
                float v1 = acc[mt][n8][h * 2 + 1] + bv1;
                if (RELU) { v0 = fmaxf(v0, 0.f); v1 = fmaxf(v1, 0.f); }
                long o = row * (long)N + col;
                if (OUT == 0) {
                    *reinterpret_cast<float2*>(Cf + zC + o) = make_float2(v0, v1);
                } else {
                    *reinterpret_cast<__half2*>(Chi + zC + o) =
                        __halves2half2(__float2half_rn(v0), __float2half_rn(v1));
                }
            }
        }
    }
}

// ---------------------------------------------------------------------------
// Launch
// ---------------------------------------------------------------------------
extern "C" void kernel_launch(void* const* d_in, const int* in_sizes, int n_in,
                              void* d_out, int out_size) {
    const int*   ids = (const int*)  d_in[0];
    const float* emb = (const float*)d_in[1];
    const float* W1  = (const float*)d_in[2];
    const float* b1  = (const float*)d_in[3];
    const float* W2  = (const float*)d_in[4];
    const float* b2  = (const float*)d_in[5];
    float* out = (float*)d_out;

    float* scores;
    __half *xhi, *xlo, *xThi, *whi, *athi, *hdhi, *w1t, *w2t;
    cudaGetSymbolAddress((void**)&scores, g_scores);
    cudaGetSymbolAddress((void**)&xhi,    g_xhi);
    cudaGetSymbolAddress((void**)&xlo,    g_xlo);
    cudaGetSymbolAddress((void**)&xThi,   g_xThi);
    cudaGetSymbolAddress((void**)&whi,    g_whi);
    cudaGetSymbolAddress((void**)&athi,   g_atthi);
    cudaGetSymbolAddress((void**)&hdhi,   g_hidhi);
    cudaGetSymbolAddress((void**)&w1t,    g_W1t);
    cudaGetSymbolAddress((void**)&w2t,    g_W2t);

    const int SM3 = 4 * 3 * TILE_BYTES;   // scores: 196608
    cudaFuncSetAttribute(hgemm_sym, cudaFuncAttributeMaxDynamicSharedMemorySize, SM3);
    cudaFuncSetAttribute(hgemm_1t<1, false, false>, cudaFuncAttributeMaxDynamicSharedMemorySize, F2_SMEM);
    cudaFuncSetAttribute(hgemm_1t<1, true,  true >, cudaFuncAttributeMaxDynamicSharedMemorySize, F2_SMEM);
    cudaFuncSetAttribute(hgemm_1t<0, true,  false>, cudaFuncAttributeMaxDynamicSharedMemorySize, F2_SMEM);

    // One-time side stream + events (created once; identical work every call)
    static cudaStream_t s2 = [] {
        cudaStream_t s; cudaStreamCreateWithFlags(&s, cudaStreamNonBlocking); return s;
    }();
    static cudaEvent_t evFork = [] {
        cudaEvent_t e; cudaEventCreateWithFlags(&e, cudaEventDisableTiming); return e;
    }();
    static cudaEvent_t evJoin = [] {
        cudaEvent_t e; cudaEventCreateWithFlags(&e, cudaEventDisableTiming); return e;
    }();

    // Fork: weight transpose runs concurrently with the attention chain
    cudaEventRecord(evFork, 0);
    cudaStreamWaitEvent(s2, evFork, 0);
    transpose_weights_kernel<<<NT1 + NT2, dim3(8, 32), 0, s2>>>(W1, W2, w1t, w2t);
    cudaEventRecord(evJoin, s2);

    // 0) embedding -> xhi, xlo, xThi in one gather pass
    {
        dim3 grid(EMBED / 32, SEQ / 32, BATCH);
        embed_xt_kernel<<<grid, dim3(8, 32)>>>(ids, emb, xhi, xlo, xThi);
    }

    // 1) scores = x @ x^T  (3-term symmetric, upper-tri + mirror)  M=N=2048 K=1024
    {
        const int ntm = SEQ / BMT;                 // 16
        dim3 grid(ntm * (ntm + 1) / 2, 1, BATCH);  // 136 x 4
        hgemm_sym<<<grid, 256, SM3>>>(
            xhi, xlo, scores, SEQ, EMBED, (long)SEQ * EMBED, (long)SEQ * SEQ, ntm);
    }

    // 2) softmax -> w hi
    softmax_kernel<<<BATCH * SEQ, 256>>>(scores, whi);

    // 3) attended = w @ x  (1-term NT, 2CTA/SM, fp16 hi out)  M=2048 N=1024 K=2048
    {
        dim3 grid((SEQ / 128) * (EMBED / 128), 1, BATCH);
        hgemm_1t<1, false, false><<<grid, 256, F2_SMEM>>>(
            whi, xThi, nullptr, nullptr, athi,
            SEQ, EMBED, SEQ,
            (long)SEQ * SEQ, (long)EMBED * SEQ, (long)SEQ * EMBED,
            SEQ / 128);
    }

    // Join: weights must be converted before FFN1
    cudaStreamWaitEvent(0, evJoin, 0);

    // 4) hidden = relu(att @ W1 + b1)  (1-term NT, 2CTA/SM, fp16 hi out)  M=8192 N=4096 K=1024
    {
        dim3 grid(((BATCH * SEQ) / 128) * (HID / 128), 1, 1);
        hgemm_1t<1, true, true><<<grid, 256, F2_SMEM>>>(
            athi, w1t, b1, nullptr, hdhi,
            BATCH * SEQ, HID, EMBED, 0, 0, 0,
            (BATCH * SEQ) / 128);
    }

    // 5) logits = hidden @ W2 + b2  (1-term NT, 2CTA/SM, fp32 out)  M=8192 N=32000 K=4096
    {
        dim3 grid(((BATCH * SEQ) / 128) * (VOCAB / 128), 1, 1);
        hgemm_1t<0, true, false><<<grid, 256, F2_SMEM>>>(
            hdhi, w2t, b2, out, nullptr,
            BATCH * SEQ, VOCAB, HID, 0, 0, 0,
            (BATCH * SEQ) / 128);
    }
}

// round 17
// speedup vs baseline: 1.1220x; 1.0007x over previous
#include <cuda_runtime.h>
#include <cuda_fp16.h>
#include <cstdint>

// Problem dims
#define BATCH 4
#define SEQ   2048
#define EMBED 1024
#define HID   4096
#define VOCAB 32000

// ---------------------------------------------------------------------------
// PTX helpers (plain sm_103-legal: cp.async / ldmatrix / mma.sync only)
// ---------------------------------------------------------------------------
__device__ __forceinline__ uint32_t smem_u32(const void* p) {
    uint32_t a;
    asm("{ .reg .u64 t; cvta.to.shared.u64 t, %1; cvt.u32.u64 %0, t; }" : "=r"(a) : "l"(p));
    return a;
}
#define CP_ASYNC16(s, g) \
    asm volatile("cp.async.cg.shared.global [%0], [%1], 16;\n" :: "r"(s), "l"(g))
#define CP_COMMIT() asm volatile("cp.async.commit_group;\n" ::: "memory")
#define CP_WAIT1()  asm volatile("cp.async.wait_group 1;\n" ::: "memory")

__device__ __forceinline__ void ldsm4(uint32_t* r, uint32_t a) {
    asm volatile("ldmatrix.sync.aligned.m8n8.x4.shared.b16 {%0,%1,%2,%3}, [%4];"
        : "=r"(r[0]), "=r"(r[1]), "=r"(r[2]), "=r"(r[3]) : "r"(a));
}
__device__ __forceinline__ void mma16816(float* c, const uint32_t* a, const uint32_t* b) {
    asm volatile(
        "mma.sync.aligned.m16n8k16.row.col.f32.f16.f16.f32 "
        "{%0,%1,%2,%3}, {%4,%5,%6,%7}, {%8,%9}, {%0,%1,%2,%3};"
        : "+f"(c[0]), "+f"(c[1]), "+f"(c[2]), "+f"(c[3])
        : "r"(a[0]), "r"(a[1]), "r"(a[2]), "r"(a[3]), "r"(b[0]), "r"(b[1]));
}

// 128B-row SW128 swizzle: row r, 16B-chunk q (0..7) -> byte offset in tile
#define SWZ(r, q) ((uint32_t)((r) * 128 + ((((q) ^ ((r) & 7))) << 4)))

// fp16 hi/lo split (hi+lo covers ~22 mantissa bits of the fp32 value)
__device__ __forceinline__ void hsplit(float v, __half& h, __half& l) {
    h = __float2half_rn(v);
    l = __float2half_rn(v - __half2float(h));
}

// ---------------------------------------------------------------------------
// Scratch (device globals)
// ---------------------------------------------------------------------------
__device__ __half g_xhi   [BATCH * SEQ * EMBED];
__device__ __half g_xlo   [BATCH * SEQ * EMBED];
__device__ __half g_xThi  [BATCH * EMBED * SEQ];
__device__ float  g_scores[BATCH * SEQ * SEQ];
__device__ __half g_whi   [BATCH * SEQ * SEQ];
__device__ __half g_atthi [BATCH * SEQ * EMBED];
__device__ __half g_hidhi [BATCH * SEQ * HID];
__device__ __half g_W1t   [HID * EMBED];
__device__ __half g_W2t   [(size_t)VOCAB * HID];

// ---------------------------------------------------------------------------
// Merged embedding gather + split + transpose.
// ---------------------------------------------------------------------------
__global__ void embed_xt_kernel(const int* __restrict__ ids, const float* __restrict__ emb,
                                __half* __restrict__ xhi, __half* __restrict__ xlo,
                                __half* __restrict__ xThi) {
    __shared__ float t[32][33];
    long z = blockIdx.z;
    const int* idz = ids + z * SEQ;
    xhi  += z * (long)SEQ * EMBED;
    xlo  += z * (long)SEQ * EMBED;
    xThi += z * (long)EMBED * SEQ;
    int c0 = blockIdx.x * 32;
    int r0 = blockIdx.y * 32;
    int tx = threadIdx.x;       // 0..7
    int ty = threadIdx.y;       // 0..31

    int id = idz[r0 + ty];
    float4 v = *reinterpret_cast<const float4*>(emb + (long)id * EMBED + c0 + 4 * tx);

    __half h0, l0, h1, l1, h2, l2, h3, l3;
    hsplit(v.x, h0, l0); hsplit(v.y, h1, l1); hsplit(v.z, h2, l2); hsplit(v.w, h3, l3);
    {
        long o = (long)(r0 + ty) * EMBED + c0 + 4 * tx;
        __half2 ph0 = __halves2half2(h0, h1), ph1 = __halves2half2(h2, h3);
        __half2 pl0 = __halves2half2(l0, l1), pl1 = __halves2half2(l2, l3);
        uint2 uh, ul;
        uh.x = *reinterpret_cast<uint32_t*>(&ph0); uh.y = *reinterpret_cast<uint32_t*>(&ph1);
        ul.x = *reinterpret_cast<uint32_t*>(&pl0); ul.y = *reinterpret_cast<uint32_t*>(&pl1);
        *reinterpret_cast<uint2*>(xhi + o) = uh;
        *reinterpret_cast<uint2*>(xlo + o) = ul;
    }

    t[ty][4 * tx + 0] = v.x;
    t[ty][4 * tx + 1] = v.y;
    t[ty][4 * tx + 2] = v.z;
    t[ty][4 * tx + 3] = v.w;
    __syncthreads();

    {
        __half2 p0 = __halves2half2(__float2half_rn(t[4 * tx + 0][ty]),
                                    __float2half_rn(t[4 * tx + 1][ty]));
        __half2 p1 = __halves2half2(__float2half_rn(t[4 * tx + 2][ty]),
                                    __float2half_rn(t[4 * tx + 3][ty]));
        uint2 o;
        o.x = *reinterpret_cast<uint32_t*>(&p0);
        o.y = *reinterpret_cast<uint32_t*>(&p1);
        *reinterpret_cast<uint2*>(xThi + (long)(c0 + ty) * SEQ + r0 + 4 * tx) = o;
    }
}

// ---------------------------------------------------------------------------
// Combined weight transpose (float4, FLAT grid):
// tiles [0, NT1) -> W1 [E,H]->[H,E]; tiles [NT1, NT1+NT2) -> W2 [H,V]->[V,H]
// ---------------------------------------------------------------------------
#define NT1 ((EMBED / 32) * (HID / 32))     // 4096
#define NT2 ((HID / 32) * (VOCAB / 32))     // 128000

__global__ void transpose_weights_kernel(const float* __restrict__ W1,
                                         const float* __restrict__ W2,
                                         __half* __restrict__ w1t,
                                         __half* __restrict__ w2t) {
    __shared__ float t[32][33];
    int T = blockIdx.x;
    const float* in; __half* outp; int R, C, tr, tc;
    if (T < NT1) {
        in = W1; outp = w1t; R = EMBED; C = HID;
        tr = T / (HID / 32); tc = T % (HID / 32);
    } else {
        T -= NT1;
        in = W2; outp = w2t; R = HID; C = VOCAB;
        tr = T / (VOCAB / 32); tc = T % (VOCAB / 32);
    }
    int c0 = tc * 32, r0 = tr * 32;
    int tx = threadIdx.x, ty = threadIdx.y;

    float4 v = *reinterpret_cast<const float4*>(in + (long)(r0 + ty) * C + c0 + 4 * tx);
    t[ty][4 * tx + 0] = v.x;
    t[ty][4 * tx + 1] = v.y;
    t[ty][4 * tx + 2] = v.z;
    t[ty][4 * tx + 3] = v.w;
    __syncthreads();

    __half2 p0 = __halves2half2(__float2half_rn(t[4 * tx + 0][ty]),
                                __float2half_rn(t[4 * tx + 1][ty]));
    __half2 p1 = __halves2half2(__float2half_rn(t[4 * tx + 2][ty]),
                                __float2half_rn(t[4 * tx + 3][ty]));
    uint2 o;
    o.x = *reinterpret_cast<uint32_t*>(&p0);
    o.y = *reinterpret_cast<uint32_t*>(&p1);
    *reinterpret_cast<uint2*>(outp + (long)(c0 + ty) * R + r0 + 4 * tx) = o;
}

// ---------------------------------------------------------------------------
// Softmax rows (fp32 in) -> fp16 hi weights only
// ---------------------------------------------------------------------------
__global__ __launch_bounds__(256)
void softmax_kernel(const float* __restrict__ scores, __half* __restrict__ whi) {
    __shared__ float red[256];
    const float* row = scores + (long)blockIdx.x * SEQ;
    __half* oh = whi + (long)blockIdx.x * SEQ;
    const int tid = threadIdx.x;

    float v[8];
    float lmax = -3.402823466e+38f;
    #pragma unroll
    for (int i = 0; i < 8; i++) { v[i] = row[tid + i * 256]; lmax = fmaxf(lmax, v[i]); }
    red[tid] = lmax; __syncthreads();
    #pragma unroll
    for (int s = 128; s > 0; s >>= 1) { if (tid < s) red[tid] = fmaxf(red[tid], red[tid + s]); __syncthreads(); }
    float m = red[0]; __syncthreads();

    float lsum = 0.f;
    #pragma unroll
    for (int i = 0; i < 8; i++) { v[i] = __expf(v[i] - m); lsum += v[i]; }
    red[tid] = lsum; __syncthreads();
    #pragma unroll
    for (int s = 128; s > 0; s >>= 1) { if (tid < s) red[tid] += red[tid + s]; __syncthreads(); }
    float inv = 1.f / red[0];
    #pragma unroll
    for (int i = 0; i < 8; i++)
        oh[tid + i * 256] = __float2half_rn(v[i] * inv);
}

// ---------------------------------------------------------------------------
// 3-term split-fp16 symmetric GEMM (scores):  C = A*A^T, upper-tri + mirror.
// CTA 128x128, BK=64, 8 warps, 3 stages. (Champion configuration.)
// ---------------------------------------------------------------------------
#define BMT 128
#define BKT 64
#define TILE_BYTES 16384    // 128 rows x 128 B

__device__ __forceinline__ void load_chunk_sym(uint32_t sbase, int st,
    const __half* __restrict__ gA0, const __half* __restrict__ gA1,
    const __half* __restrict__ gB0, const __half* __restrict__ gB1,
    int K, int k0, int tid)
{
    uint32_t s0 = sbase + (uint32_t)(st * 4 * TILE_BYTES);
    #pragma unroll
    for (int it = 0; it < 4; it++) {
        int idx = tid + it * 256;
        int r = idx >> 3, c = idx & 7;
        uint32_t so = SWZ(r, c);
        long go = (long)r * K + k0 + c * 8;
        CP_ASYNC16(s0 + 0 * TILE_BYTES + so, gA0 + go);
        CP_ASYNC16(s0 + 1 * TILE_BYTES + so, gA1 + go);
        CP_ASYNC16(s0 + 2 * TILE_BYTES + so, gB0 + go);
        CP_ASYNC16(s0 + 3 * TILE_BYTES + so, gB1 + go);
    }
}

__global__ __launch_bounds__(256, 1)
void hgemm_sym(const __half* __restrict__ A0, const __half* __restrict__ A1,
               float* __restrict__ Cf, int N, int K, long sA, long sC, int ntm)
{
    extern __shared__ char smem[];
    const uint32_t sbase = smem_u32(smem);
    const int tid  = threadIdx.x;
    const int wid  = tid >> 5, lane = tid & 31;
    const int wm   = wid & 1,  wn   = wid >> 1;

    int t0 = blockIdx.x, i0 = 0;
    while (t0 >= ntm - i0) { t0 -= ntm - i0; i0++; }
    int pm = i0, pn = i0 + t0;
    long m0 = (long)pm * BMT, n0 = (long)pn * BMT;
    long zb = blockIdx.z;
    const __half* gA0 = A0 + zb * sA + m0 * K;
    const __half* gA1 = A1 + zb * sA + m0 * K;
    const __half* gB0 = A0 + zb * sA + n0 * K;
    const __half* gB1 = A1 + zb * sA + n0 * K;

    float acc[4][4][4];
    #pragma unroll
    for (int i = 0; i < 4; i++)
        #pragma unroll
        for (int j = 0; j < 4; j++)
            #pragma unroll
            for (int k = 0; k < 4; k++) acc[i][j][k] = 0.f;

    const int ar = lane & 15;
    const int ak = (lane >> 4) << 3;
    const int br = ((lane >> 4) << 3) + (lane & 7);
    const int bk = ((lane >> 3) & 1) << 3;

    load_chunk_sym(sbase, 0, gA0, gA1, gB0, gB1, K, 0, tid);   CP_COMMIT();
    load_chunk_sym(sbase, 1, gA0, gA1, gB0, gB1, K, BKT, tid); CP_COMMIT();

    const int nc = K / BKT;
    for (int c = 0; c < nc; c++) {
        CP_WAIT1();
        __syncthreads();
        if (c + 2 < nc)
            load_chunk_sym(sbase, (c + 2) % 3, gA0, gA1, gB0, gB1, K, (c + 2) * BKT, tid);
        CP_COMMIT();

        uint32_t s0 = sbase + (uint32_t)((c % 3) * 4 * TILE_BYTES);
        #pragma unroll
        for (int kb = 0; kb < BKT; kb += 16) {
            uint32_t a0f[4][4], a1f[4][4], b0f[2][4], b1f[2][4];
            int aq = (kb + ak) >> 3;
            int bq = (kb + bk) >> 3;
            #pragma unroll
            for (int mt = 0; mt < 4; mt++) {
                int r = wm * 64 + mt * 16 + ar;
                uint32_t ad = s0 + SWZ(r, aq);
                ldsm4(a0f[mt], ad);
                ldsm4(a1f[mt], ad + TILE_BYTES);
            }
            #pragma unroll
            for (int nt = 0; nt < 2; nt++) {
                int r = wn * 32 + nt * 16 + br;
                uint32_t bd = s0 + 2 * TILE_BYTES + SWZ(r, bq);
                ldsm4(b0f[nt], bd);
                ldsm4(b1f[nt], bd + TILE_BYTES);
            }
            #pragma unroll
            for (int mt = 0; mt < 4; mt++)
                #pragma unroll
                for (int n8 = 0; n8 < 4; n8++) {
                    const uint32_t* b = &b0f[n8 >> 1][(n8 & 1) * 2];
                    mma16816(acc[mt][n8], a0f[mt], b);
                    mma16816(acc[mt][n8], a1f[mt], b);
                    mma16816(acc[mt][n8], a0f[mt], &b1f[n8 >> 1][(n8 & 1) * 2]);
                }
        }
    }

    // ---- epilogue (direct tile) ----
    long zC = zb * sC;
    int rb = lane >> 2;
    int cb = (lane & 3) * 2;
    #pragma unroll
    for (int mt = 0; mt < 4; mt++) {
        #pragma unroll
        for (int n8 = 0; n8 < 4; n8++) {
            long col = n0 + wn * 32 + n8 * 8 + cb;
            #pragma unroll
            for (int h = 0; h < 2; h++) {
                long row = m0 + wm * 64 + mt * 16 + rb + h * 8;
                *reinterpret_cast<float2*>(Cf + zC + row * (long)N + col) =
                    make_float2(acc[mt][n8][h * 2 + 0], acc[mt][n8][h * 2 + 1]);
            }
        }
    }

    // ---- mirror transposed tile at (pn, pm) ----
    if (pm != pn) {
        __syncthreads();
        float* stg = reinterpret_cast<float*>(smem);   // 128 x 129 floats
        #pragma unroll
        for (int mt = 0; mt < 4; mt++)
            #pragma unroll
            for (int n8 = 0; n8 < 4; n8++) {
                int colb = wn * 32 + n8 * 8 + cb;
                #pragma unroll
                for (int h = 0; h < 2; h++) {
                    int rowb = wm * 64 + mt * 16 + rb + h * 8;
                    stg[rowb * 129 + colb]     = acc[mt][n8][h * 2 + 0];
                    stg[rowb * 129 + colb + 1] = acc[mt][n8][h * 2 + 1];
                }
            }
        __syncthreads();
        #pragma unroll
        for (int it = 0; it < 64; it++) {
            int idx = tid + it * 256;
            int rr = idx >> 7, cc = idx & 127;
            Cf[zC + (n0 + rr) * (long)N + m0 + cc] = stg[cc * 129 + rr];
        }
    }
}

// ---------------------------------------------------------------------------
// 1-term HMMA GEMM (attended, FFN1, FFN2): 2 CTAs/SM, CTA 128x128, BK=64,
// 8 warps, 3 stages (96 KB/CTA).  OUT=0: fp32.  OUT=1: fp16 hi.  Batched via z.
// ---------------------------------------------------------------------------
#define F2_STAGE (2 * TILE_BYTES)      // A tile + B tile = 32 KB
#define F2_SMEM  (3 * F2_STAGE)        // 98304

__device__ __forceinline__ void load_chunk_1t(uint32_t sbase, int st,
    const __half* __restrict__ gA, const __half* __restrict__ gB,
    int K, int k0, int tid)
{
    uint32_t s0 = sbase + (uint32_t)(st * F2_STAGE);
    #pragma unroll
    for (int it = 0; it < 4; it++) {
        int idx = tid + it * 256;
        int r = idx >> 3, c = idx & 7;
        uint32_t so = SWZ(r, c);
        long go = (long)r * K + k0 + c * 8;
        CP_ASYNC16(s0 + so, gA + go);
        CP_ASYNC16(s0 + TILE_BYTES + so, gB + go);
    }
}

template<int OUT, bool BIAS, bool RELU>
__global__ __launch_bounds__(256, 2)
void hgemm_1t(const __half* __restrict__ A0, const __half* __restrict__ B0,
              const float* __restrict__ bias,
              float* __restrict__ Cf, __half* __restrict__ Chi,
              int M, int N, int K, long sA, long sB, long sC, int ntm)
{
    extern __shared__ char smem[];
    const uint32_t sbase = smem_u32(smem);
    const int tid  = threadIdx.x;
    const int wid  = tid >> 5, lane = tid & 31;
    const int wm   = wid & 1,  wn   = wid >> 1;

    int pm = blockIdx.x % ntm, pn = blockIdx.x / ntm;
    long m0 = (long)pm * 128, n0 = (long)pn * 128;
    long zb = blockIdx.z;
    const __half* gA = A0 + zb * sA + m0 * K;
    const __half* gB = B0 + zb * sB + n0 * K;

    float acc[4][4][4];
    #pragma unroll
    for (int i = 0; i < 4; i++)
        #pragma unroll
        for (int j = 0; j < 4; j++)
            #pragma unroll
            for (int k = 0; k < 4; k++) acc[i][j][k] = 0.f;

    const int ar = lane & 15;
    const int ak = (lane >> 4) << 3;
    const int br = ((lane >> 4) << 3) + (lane & 7);
    const int bk = ((lane >> 3) & 1) << 3;

    load_chunk_1t(sbase, 0, gA, gB, K, 0, tid);    CP_COMMIT();
    load_chunk_1t(sbase, 1, gA, gB, K, BKT, tid);  CP_COMMIT();

    const int nc = K / BKT;
    for (int c = 0; c < nc; c++) {
        CP_WAIT1();
        __syncthreads();
        if (c + 2 < nc)
            load_chunk_1t(sbase, (c + 2) % 3, gA, gB, K, (c + 2) * BKT, tid);
        CP_COMMIT();

        uint32_t s0 = sbase + (uint32_t)((c % 3) * F2_STAGE);
        #pragma unroll
        for (int kb = 0; kb < BKT; kb += 16) {
            uint32_t af[4][4], bf[2][4];
            int aq = (kb + ak) >> 3;
            int bq = (kb + bk) >> 3;
            #pragma unroll
            for (int mt = 0; mt < 4; mt++) {
                int r = wm * 64 + mt * 16 + ar;
                ldsm4(af[mt], s0 + SWZ(r, aq));
            }
            #pragma unroll
            for (int nt = 0; nt < 2; nt++) {
                int r = wn * 32 + nt * 16 + br;
                ldsm4(bf[nt], s0 + TILE_BYTES + SWZ(r, bq));
            }
            #pragma unroll
            for (int mt = 0; mt < 4; mt++)
                #pragma unroll
                for (int n8 = 0; n8 < 4; n8++)
                    mma16816(acc[mt][n8], af[mt], &bf[n8 >> 1][(n8 & 1) * 2]);
        }
    }

    // ---- epilogue ----
    long zC = zb * sC;
    int rb = lane >> 2;
    int cb = (lane & 3) * 2;
    #pragma unroll
    for (int mt = 0; mt < 4; mt++) {
        #pragma unroll
        for (int n8 = 0; n8 < 4; n8++) {
            long col = n0 + wn * 32 + n8 * 8 + cb;
            float bv0 = 0.f, bv1 = 0.f;
            if (BIAS) { bv0 = bias[col]; bv1 = bias[col + 1]; }
            #pragma unroll
            for (int h = 0; h < 2; h++) {
                long row = m0 + wm * 64 + mt * 16 + rb + h * 8;
                float v0 = acc[mt][n8][h * 2 + 0] + bv0;
                float v1 = acc[mt][n8][h * 2 + 1] + bv1;
                if (RELU) { v0 = fmaxf(v0, 0.f); v1 = fmaxf(v1, 0.f); }
                long o = row * (long)N + col;
                if (OUT == 0) {
                    *reinterpret_cast<float2*>(Cf + zC + o) = make_float2(v0, v1);
                } else {
                    *reinterpret_cast<__half2*>(Chi + zC + o) =
                        __halves2half2(__float2half_rn(v0), __float2half_rn(v1));
                }
            }
        }
    }
}

// ---------------------------------------------------------------------------
// Launch
// ---------------------------------------------------------------------------
extern "C" void kernel_launch(void* const* d_in, const int* in_sizes, int n_in,
                              void* d_out, int out_size) {
    const int*   ids = (const int*)  d_in[0];
    const float* emb = (const float*)d_in[1];
    const float* W1  = (const float*)d_in[2];
    const float* b1  = (const float*)d_in[3];
    const float* W2  = (const float*)d_in[4];
    const float* b2  = (const float*)d_in[5];
    float* out = (float*)d_out;

    float* scores;
    __half *xhi, *xlo, *xThi, *whi, *athi, *hdhi, *w1t, *w2t;
    cudaGetSymbolAddress((void**)&scores, g_scores);
    cudaGetSymbolAddress((void**)&xhi,    g_xhi);
    cudaGetSymbolAddress((void**)&xlo,    g_xlo);
    cudaGetSymbolAddress((void**)&xThi,   g_xThi);
    cudaGetSymbolAddress((void**)&whi,    g_whi);
    cudaGetSymbolAddress((void**)&athi,   g_atthi);
    cudaGetSymbolAddress((void**)&hdhi,   g_hidhi);
    cudaGetSymbolAddress((void**)&w1t,    g_W1t);
    cudaGetSymbolAddress((void**)&w2t,    g_W2t);

    const int SM3 = 4 * 3 * TILE_BYTES;   // scores: 196608
    cudaFuncSetAttribute(hgemm_sym, cudaFuncAttributeMaxDynamicSharedMemorySize, SM3);
    cudaFuncSetAttribute(hgemm_1t<1, false, false>, cudaFuncAttributeMaxDynamicSharedMemorySize, F2_SMEM);
    cudaFuncSetAttribute(hgemm_1t<1, true,  true >, cudaFuncAttributeMaxDynamicSharedMemorySize, F2_SMEM);
    cudaFuncSetAttribute(hgemm_1t<0, true,  false>, cudaFuncAttributeMaxDynamicSharedMemorySize, F2_SMEM);

    // One-time side stream + events (created once; identical work every call)
    static cudaStream_t s2 = [] {
        cudaStream_t s; cudaStreamCreateWithFlags(&s, cudaStreamNonBlocking); return s;
    }();
    static cudaEvent_t evFork = [] {
        cudaEvent_t e; cudaEventCreateWithFlags(&e, cudaEventDisableTiming); return e;
    }();
    static cudaEvent_t evJoin = [] {
        cudaEvent_t e; cudaEventCreateWithFlags(&e, cudaEventDisableTiming); return e;
    }();
    static cudaEvent_t evF1h0 = [] {
        cudaEvent_t e; cudaEventCreateWithFlags(&e, cudaEventDisableTiming); return e;
    }();
    static cudaEvent_t evF2h0 = [] {
        cudaEvent_t e; cudaEventCreateWithFlags(&e, cudaEventDisableTiming); return e;
    }();

    const int MH = (BATCH * SEQ) / 2;     // 4096 rows per FFN half

    // Fork: weight transpose runs concurrently with the attention chain
    cudaEventRecord(evFork, 0);
    cudaStreamWaitEvent(s2, evFork, 0);
    transpose_weights_kernel<<<NT1 + NT2, dim3(8, 32), 0, s2>>>(W1, W2, w1t, w2t);
    cudaEventRecord(evJoin, s2);

    // 0) embedding -> xhi, xlo, xThi in one gather pass
    {
        dim3 grid(EMBED / 32, SEQ / 32, BATCH);
        embed_xt_kernel<<<grid, dim3(8, 32)>>>(ids, emb, xhi, xlo, xThi);
    }

    // 1) scores = x @ x^T  (3-term symmetric, upper-tri + mirror)
    {
        const int ntm = SEQ / BMT;                 // 16
        dim3 grid(ntm * (ntm + 1) / 2, 1, BATCH);  // 136 x 4
        hgemm_sym<<<grid, 256, SM3>>>(
            xhi, xlo, scores, SEQ, EMBED, (long)SEQ * EMBED, (long)SEQ * SEQ, ntm);
    }

    // 2) softmax -> w hi
    softmax_kernel<<<BATCH * SEQ, 256>>>(scores, whi);

    // 3) attended = w @ x  (1-term NT, 2CTA/SM, fp16 hi out)
    {
        dim3 grid((SEQ / 128) * (EMBED / 128), 1, BATCH);
        hgemm_1t<1, false, false><<<grid, 256, F2_SMEM>>>(
            whi, xThi, nullptr, nullptr, athi,
            SEQ, EMBED, SEQ,
            (long)SEQ * SEQ, (long)EMBED * SEQ, (long)SEQ * EMBED,
            SEQ / 128);
    }

    // Join: weights must be converted before FFN1
    cudaStreamWaitEvent(0, evJoin, 0);

    // 4a) FFN1 half0: hidden[0:4096) = relu(att[0:4096) @ W1 + b1)
    {
        dim3 grid((MH / 128) * (HID / 128), 1, 1);
        hgemm_1t<1, true, true><<<grid, 256, F2_SMEM>>>(
            athi, w1t, b1, nullptr, hdhi,
            MH, HID, EMBED, 0, 0, 0, MH / 128);
    }
    cudaEventRecord(evF1h0, 0);

    // 4b) FFN1 half1 (main stream)
    {
        dim3 grid((MH / 128) * (HID / 128), 1, 1);
        hgemm_1t<1, true, true><<<grid, 256, F2_SMEM>>>(
            athi + (long)MH * EMBED, w1t, b1, nullptr, hdhi + (long)MH * HID,
            MH, HID, EMBED, 0, 0, 0, MH / 128);
    }

    // 5a) FFN2 half0 on side stream, overlapping FFN1 half1
    cudaStreamWaitEvent(s2, evF1h0, 0);
    {
        dim3 grid((MH / 128) * (VOCAB / 128), 1, 1);
        hgemm_1t<0, true, false><<<grid, 256, F2_SMEM, s2>>>(
            hdhi, w2t, b2, out, nullptr,
            MH, VOCAB, HID, 0, 0, 0, MH / 128);
    }
    cudaEventRecord(evF2h0, s2);

    // 5b) FFN2 half1 (main stream, after FFN1 half1)
    {
        dim3 grid((MH / 128) * (VOCAB / 128), 1, 1);
        hgemm_1t<0, true, false><<<grid, 256, F2_SMEM>>>(
            hdhi + (long)MH * HID, w2t, b2, out + (long)MH * VOCAB, nullptr,
            MH, VOCAB, HID, 0, 0, 0, MH / 128);
    }

    // Join side stream before graph end
    cudaStreamWaitEvent(0, evF2h0, 0);
}